// round 4
// baseline (speedup 1.0000x reference)
#include <cuda_runtime.h>
#include <math.h>
#include <stdint.h>

#define NN 50000
#define EE 400000
#define RR 500
#define XS 100
#define GS 100

static __device__ __constant__ float kNEG = 0.01f;
static __device__ __constant__ float kEPS = 1e-12f;

// ------------------------- scratch (device globals) -------------------------
__device__ float d_xn[NN * XS];
__device__ float d_uA[NN * 128];
__device__ float d_vA[NN * 128];
__device__ float d_uB[NN * 128];
__device__ float d_vB[NN * 128];
__device__ float d_accA[NN * 128];
__device__ float d_accB[NN * 128];
__device__ float d_salA[NN * 2];
__device__ float d_salB[NN * 2];
__device__ float d_h[NN * 128];
__device__ float d_ent[NN * 64];
__device__ float d_wA[RR * 128];
__device__ float d_wB[RR * 128];
__device__ float d_auA[NN * 2];
__device__ float d_avA[NN * 2];
__device__ float d_auB[NN * 2];
__device__ float d_avB[NN * 2];
__device__ float d_awA[RR * 2];
__device__ float d_awB[RR * 2];
__device__ float d_ebA[EE * 2];
__device__ float d_ebB[EE * 2];
__device__ float d_denA[NN * 2];
__device__ float d_denB[NN * 2];
__device__ float d_q[8 * 128];

// ------------------------- helpers -------------------------
__device__ __forceinline__ float wsum(float v) {
#pragma unroll
    for (int o = 16; o > 0; o >>= 1) v += __shfl_xor_sync(0xffffffffu, v, o);
    return v;
}

__device__ __forceinline__ uint32_t tf32_hi(float v) {
    uint32_t h;
    asm("cvt.rna.tf32.f32 %0, %1;" : "=r"(h) : "f"(v));
    return h;
}

__device__ __forceinline__ void mma_tf32(float* d, const uint32_t* a, const uint32_t* b) {
    asm volatile(
        "mma.sync.aligned.m16n8k8.row.col.f32.tf32.tf32.f32 "
        "{%0,%1,%2,%3}, {%4,%5,%6,%7}, {%8,%9}, {%0,%1,%2,%3};"
        : "+f"(d[0]), "+f"(d[1]), "+f"(d[2]), "+f"(d[3])
        : "r"(a[0]), "r"(a[1]), "r"(a[2]), "r"(a[3]), "r"(b[0]), "r"(b[1]));
}

// L2-normalize rows of x [NN, XS]; blockDim = 128, one block per row
__global__ void norm_x(const float* __restrict__ x, float* __restrict__ xn) {
    int i = blockIdx.x;
    int j = threadIdx.x;
    float v = (j < XS) ? x[i * XS + j] : 0.f;
    float s = wsum(v * v);
    __shared__ float sm[4];
    if ((j & 31) == 0) sm[j >> 5] = s;
    __syncthreads();
    float tot = sm[0] + sm[1] + sm[2] + sm[3];
    if (j < XS) xn[i * XS + j] = v / fmaxf(sqrtf(tot), kEPS);
}

// ------------------- tensor-core 4-projection GEMM (tf32 split) -------------
// y=0..3: C_y[M x 128] = A @ Wsel[:, koff:koff+K].T
// Block tile 128x128, 8 warps each 64(m) x 32(n), K-step 16.
// Accuracy: A,B split into tf32 hi+lo; D = Ah*Bh + Ah*Bl + Al*Bh (fp32-class).
__global__ __launch_bounds__(256, 1) void gemm4_tc(
    const float* __restrict__ A, int lda, int K,
    const float* __restrict__ Wi, const float* __restrict__ Wo, int ldw,
    float* __restrict__ uA, float* __restrict__ vA,
    float* __restrict__ uB, float* __restrict__ vB, int M)
{
    int y = blockIdx.y;
    const float* W = (y < 2) ? Wi : Wo;
    int koff = (y & 1) ? K : 0;
    float* C = (y == 0) ? uA : (y == 1) ? vA : (y == 2) ? uB : vB;

    __shared__ float Ah[128][20];
    __shared__ float Al[128][20];
    __shared__ float Bh[128][20];
    __shared__ float Bl[128][20];

    int m0 = blockIdx.x * 128;
    int tid = threadIdx.x;
    int lane = tid & 31;
    int wid = tid >> 5;
    int wm = wid >> 2;        // 0..1 -> 64-row group
    int wn = wid & 3;         // 0..3 -> 32-col group
    int g = lane >> 2;        // groupID
    int c = lane & 3;         // thread-in-group

    float acc[4][4][4] = {};  // [m-tile][n-tile][reg]

    int lrow = tid >> 1;
    int lkb = (tid & 1) * 8;

    for (int k0 = 0; k0 < K; k0 += 16) {
        // stage A tile (128 x 16), split hi/lo
        {
            int gm = m0 + lrow;
            const float* ap = A + (size_t)gm * lda + k0 + lkb;
            bool rok = (gm < M);
#pragma unroll
            for (int i = 0; i < 8; i++) {
                int gk = k0 + lkb + i;
                float v = (rok && gk < K) ? ap[i] : 0.f;
                uint32_t hv = tf32_hi(v);
                float hf = __uint_as_float(hv);
                Ah[lrow][lkb + i] = hf;
                Al[lrow][lkb + i] = v - hf;
            }
        }
        // stage B tile (128 n-rows x 16 k), split hi/lo
        {
            const float* wp = W + (size_t)lrow * ldw + koff + k0 + lkb;
#pragma unroll
            for (int i = 0; i < 8; i++) {
                int gk = k0 + lkb + i;
                float v = (gk < K) ? wp[i] : 0.f;
                uint32_t hv = tf32_hi(v);
                float hf = __uint_as_float(hv);
                Bh[lrow][lkb + i] = hf;
                Bl[lrow][lkb + i] = v - hf;
            }
        }
        __syncthreads();

#pragma unroll
        for (int ks = 0; ks < 16; ks += 8) {
            uint32_t ah[4][4], al[4][4], bh[4][2], bl[4][2];
#pragma unroll
            for (int i = 0; i < 4; i++) {
                int r0 = wm * 64 + i * 16 + g;
                ah[i][0] = __float_as_uint(Ah[r0][ks + c]);
                ah[i][1] = __float_as_uint(Ah[r0 + 8][ks + c]);
                ah[i][2] = __float_as_uint(Ah[r0][ks + c + 4]);
                ah[i][3] = __float_as_uint(Ah[r0 + 8][ks + c + 4]);
                al[i][0] = __float_as_uint(Al[r0][ks + c]);
                al[i][1] = __float_as_uint(Al[r0 + 8][ks + c]);
                al[i][2] = __float_as_uint(Al[r0][ks + c + 4]);
                al[i][3] = __float_as_uint(Al[r0 + 8][ks + c + 4]);
            }
#pragma unroll
            for (int j = 0; j < 4; j++) {
                int n = wn * 32 + j * 8 + g;
                bh[j][0] = __float_as_uint(Bh[n][ks + c]);
                bh[j][1] = __float_as_uint(Bh[n][ks + c + 4]);
                bl[j][0] = __float_as_uint(Bl[n][ks + c]);
                bl[j][1] = __float_as_uint(Bl[n][ks + c + 4]);
            }
#pragma unroll
            for (int i = 0; i < 4; i++)
#pragma unroll
                for (int j = 0; j < 4; j++) {
                    mma_tf32(acc[i][j], ah[i], bh[j]);
                    mma_tf32(acc[i][j], ah[i], bl[j]);
                    mma_tf32(acc[i][j], al[i], bh[j]);
                }
        }
        __syncthreads();
    }

    // epilogue: D frag (m16n8 f32): d0=(g, c*2) d1=(g, c*2+1) d2=(g+8, c*2) d3=(g+8, c*2+1)
#pragma unroll
    for (int i = 0; i < 4; i++) {
        int r0 = m0 + wm * 64 + i * 16 + g;
        int r1 = r0 + 8;
#pragma unroll
        for (int j = 0; j < 4; j++) {
            int cb = wn * 32 + j * 8 + c * 2;
            if (r0 < M) {
                float2 v = make_float2(acc[i][j][0], acc[i][j][1]);
                *(float2*)&C[(size_t)r0 * 128 + cb] = v;
            }
            if (r1 < M) {
                float2 v = make_float2(acc[i][j][2], acc[i][j][3]);
                *(float2*)&C[(size_t)r1 * 128 + cb] = v;
            }
        }
    }
}

// C[M x N] = A[M x K] @ W.T (+bias) — entity layer
__global__ __launch_bounds__(256) void gemm_wt(
    const float* __restrict__ A, int lda,
    const float* __restrict__ W, int ldw, int K,
    const float* __restrict__ bias,
    float* __restrict__ C, int ldc, int M)
{
    __shared__ float As[64][17];
    __shared__ float Bs[16][65];
    int m0 = blockIdx.x * 64, n0 = blockIdx.y * 64;
    int tx = threadIdx.x & 15, ty = threadIdx.x >> 4;
    float acc[4][4] = {};
    for (int k0 = 0; k0 < K; k0 += 16) {
#pragma unroll
        for (int i = 0; i < 4; i++) {
            int li = threadIdx.x + i * 256;
            int k = li & 15, m = li >> 4;
            int gm = m0 + m, gk = k0 + k;
            As[m][k] = (gm < M && gk < K) ? A[gm * lda + gk] : 0.f;
        }
#pragma unroll
        for (int i = 0; i < 4; i++) {
            int li = threadIdx.x + i * 256;
            int k = li & 15, n = li >> 4;
            int gk = k0 + k;
            Bs[k][n] = (gk < K) ? W[(n0 + n) * ldw + gk] : 0.f;
        }
        __syncthreads();
#pragma unroll
        for (int k = 0; k < 16; k++) {
            float a[4], b[4];
#pragma unroll
            for (int i = 0; i < 4; i++) a[i] = As[ty * 4 + i][k];
#pragma unroll
            for (int j = 0; j < 4; j++) b[j] = Bs[k][tx * 4 + j];
#pragma unroll
            for (int i = 0; i < 4; i++)
#pragma unroll
                for (int j = 0; j < 4; j++)
                    acc[i][j] = fmaf(a[i], b[j], acc[i][j]);
        }
        __syncthreads();
    }
#pragma unroll
    for (int i = 0; i < 4; i++) {
        int gm = m0 + ty * 4 + i;
        if (gm >= M) continue;
#pragma unroll
        for (int j = 0; j < 4; j++) {
            int gn = n0 + tx * 4 + j;
            C[gm * ldc + gn] = acc[i][j] + bias[gn];
        }
    }
}

// q[y][k] = sum_c att[h*64+c] * W[h*64+c, koff+k]; y = dir*4 + sel*2 + h
__global__ void qprep(const float* __restrict__ Wi, const float* __restrict__ Wo,
                      int ldw, int K,
                      const float* __restrict__ ai, const float* __restrict__ ao,
                      float* __restrict__ q)
{
    int y = blockIdx.x, k = threadIdx.x;
    const float* W = (y < 4) ? Wi : Wo;
    const float* att = (y < 4) ? ai : ao;
    int sel = (y >> 1) & 1, h = y & 1;
    int koff = sel * K;
    float s = 0.f;
    if (k < K)
        for (int c = 0; c < 64; c++)
            s = fmaf(att[h * 64 + c], W[(h * 64 + c) * ldw + koff + k], s);
    q[y * 128 + k] = (k < K) ? s : 0.f;
}

// One pass over A computing au/av for both directions. Warp per node.
__global__ __launch_bounds__(256) void auav(
    const float* __restrict__ A, int lda, int K, const float* __restrict__ q,
    float* __restrict__ auA, float* __restrict__ avA,
    float* __restrict__ auB, float* __restrict__ avB, int M)
{
    int m = blockIdx.x * 8 + (threadIdx.x >> 5);
    if (m >= M) return;
    int l = threadIdx.x & 31;
    float s[8] = {};
    for (int k = l; k < K; k += 32) {
        float a = A[m * lda + k];
#pragma unroll
        for (int y = 0; y < 8; y++) s[y] = fmaf(a, q[y * 128 + k], s[y]);
    }
#pragma unroll
    for (int y = 0; y < 8; y++) {
#pragma unroll
        for (int o = 16; o > 0; o >>= 1) s[y] += __shfl_xor_sync(0xffffffffu, s[y], o);
    }
    if (l == 0) {
        auA[m * 2 + 0] = s[0]; auA[m * 2 + 1] = s[1];
        avA[m * 2 + 0] = s[2]; avA[m * 2 + 1] = s[3];
        auB[m * 2 + 0] = s[4]; auB[m * 2 + 1] = s[5];
        avB[m * 2 + 0] = s[6]; avB[m * 2 + 1] = s[7];
    }
}

// Relation projection for both directions + fused aw reduction.
__global__ void relproj2(const float* __restrict__ g,
                         const float* __restrict__ Wi, const float* __restrict__ bi,
                         const float* __restrict__ ai,
                         const float* __restrict__ Wo, const float* __restrict__ bo,
                         const float* __restrict__ ao,
                         int ldw, int koff,
                         float* __restrict__ wA, float* __restrict__ wB,
                         float* __restrict__ awA, float* __restrict__ awB)
{
    int r = blockIdx.x, y = blockIdx.y;
    const float* W = y ? Wo : Wi;
    const float* b = y ? bo : bi;
    const float* att = y ? ao : ai;
    float* wout = y ? wB : wA;
    float* awout = y ? awB : awA;
    __shared__ float gs[GS];
    int n = threadIdx.x;
    if (n < GS) gs[n] = g[r * GS + n];
    __syncthreads();
    float acc = b[n];
    const float* wr = W + n * ldw + koff;
#pragma unroll 4
    for (int k = 0; k < GS; k++) acc = fmaf(wr[k], gs[k], acc);
    wout[r * 128 + n] = acc;
    float s = wsum(acc * att[n]);
    __shared__ float sm[4];
    if ((n & 31) == 0) sm[n >> 5] = s;
    __syncthreads();
    if (n == 0) awout[r * 2 + 0] = sm[0] + sm[1];
    if (n == 64) awout[r * 2 + 1] = sm[2] + sm[3];
}

// g_prime: block per relation
__global__ void relproj_out(const float* __restrict__ g, const float* __restrict__ Wr,
                            const float* __restrict__ br, float* __restrict__ out)
{
    int r = blockIdx.x;
    __shared__ float gs[GS];
    int n = threadIdx.x;
    if (n < GS) gs[n] = g[r * GS + n];
    __syncthreads();
    float acc = br[n];
    const float* wr = Wr + n * GS;
#pragma unroll 4
    for (int k = 0; k < GS; k++) acc = fmaf(wr[k], gs[k], acc);
    out[r * 128 + n] = acc;
}

// Fused pass A for both directions: one thread per edge.
__global__ __launch_bounds__(256) void pass_a2(
    const int* __restrict__ rowp, const int* __restrict__ colp, const int* __restrict__ et,
    const float* __restrict__ auA, const float* __restrict__ avA, const float* __restrict__ awA,
    const float* __restrict__ auB, const float* __restrict__ avB, const float* __restrict__ awB,
    float* __restrict__ ebA, float* __restrict__ ebB,
    float* __restrict__ denA, float* __restrict__ denB)
{
    int e = blockIdx.x * blockDim.x + threadIdx.x;
    if (e >= EE) return;
    int r = rowp[e], c = colp[e], t = et[e];
#pragma unroll
    for (int h = 0; h < 2; h++) {
        float a = auA[r * 2 + h] + avA[c * 2 + h] + awA[t * 2 + h];
        a = (a > 0.f) ? a : kNEG * a;
        float ex = expf(a);
        ebA[e * 2 + h] = ex;
        atomicAdd(&denA[r * 2 + h], ex);
        float b = auB[c * 2 + h] + avB[r * 2 + h] + awB[t * 2 + h];
        b = (b > 0.f) ? b : kNEG * b;
        float exb = expf(b);
        ebB[e * 2 + h] = exb;
        atomicAdd(&denB[c * 2 + h], exb);
    }
}

// Fused pass B for both directions: warp per edge.
__global__ __launch_bounds__(256) void pass_b2(
    const int* __restrict__ rowp, const int* __restrict__ colp, const int* __restrict__ et,
    const float* __restrict__ uA, const float* __restrict__ wA,
    const float* __restrict__ uB, const float* __restrict__ wB,
    const float* __restrict__ ebA, const float* __restrict__ denA,
    const float* __restrict__ ebB, const float* __restrict__ denB,
    float* __restrict__ accA, float* __restrict__ salA,
    float* __restrict__ accB, float* __restrict__ salB)
{
    int e = blockIdx.x * 8 + (threadIdx.x >> 5);
    if (e >= EE) return;
    int l = threadIdx.x & 31;
    int r = rowp[e], c = colp[e], t = et[e];
    int h = l >> 4;
    float aA = ebA[e * 2 + h] / denA[r * 2 + h];
    float aB = ebB[e * 2 + h] / denB[c * 2 + h];

    {
        float4 uv = ((const float4*)(uA + (size_t)r * 128))[l];
        float4 wv = ((const float4*)(wA + (size_t)t * 128))[l];
        float4 o;
        o.x = aA * (uv.x + wv.x); o.y = aA * (uv.y + wv.y);
        o.z = aA * (uv.z + wv.z); o.w = aA * (uv.w + wv.w);
        float* dst = accA + (size_t)c * 128 + l * 4;
        asm volatile("red.global.add.v4.f32 [%0], {%1, %2, %3, %4};"
                     :: "l"(dst), "f"(o.x), "f"(o.y), "f"(o.z), "f"(o.w) : "memory");
    }
    {
        float4 uv = ((const float4*)(uB + (size_t)c * 128))[l];
        float4 wv = ((const float4*)(wB + (size_t)t * 128))[l];
        float4 o;
        o.x = aB * (uv.x + wv.x); o.y = aB * (uv.y + wv.y);
        o.z = aB * (uv.z + wv.z); o.w = aB * (uv.w + wv.w);
        float* dst = accB + (size_t)r * 128 + l * 4;
        asm volatile("red.global.add.v4.f32 [%0], {%1, %2, %3, %4};"
                     :: "l"(dst), "f"(o.x), "f"(o.y), "f"(o.z), "f"(o.w) : "memory");
    }
    if (l == 0)  { atomicAdd(&salA[c * 2 + 0], aA); atomicAdd(&salB[r * 2 + 0], aB); }
    if (l == 16) { atomicAdd(&salA[c * 2 + 1], aA); atomicAdd(&salB[r * 2 + 1], aB); }
}

// out = l2norm_per_head(leaky(0.5*(accA + salA*vA) + 0.5*(accB + salB*vB)))
__global__ void combine(const float* __restrict__ accA, const float* __restrict__ salA,
                        const float* __restrict__ vA,
                        const float* __restrict__ accB, const float* __restrict__ salB,
                        const float* __restrict__ vB,
                        float* __restrict__ out)
{
    int i = blockIdx.x, j = threadIdx.x;
    int h = j >> 6;
    float a = accA[i * 128 + j] + salA[i * 2 + h] * vA[i * 128 + j];
    float b = accB[i * 128 + j] + salB[i * 2 + h] * vB[i * 128 + j];
    float v = 0.5f * (a + b);
    v = (v > 0.f) ? v : kNEG * v;
    float s = wsum(v * v);
    __shared__ float sm[4];
    if ((j & 31) == 0) sm[j >> 5] = s;
    __syncthreads();
    float tot = sm[h * 2] + sm[h * 2 + 1];
    out[i * 128 + j] = v / fmaxf(sqrtf(tot), kEPS);
}

// h_prime = l2norm_128(ent broadcast over heads + h)
__global__ void final_k(const float* __restrict__ ent, const float* __restrict__ h,
                        float* __restrict__ out)
{
    int i = blockIdx.x, j = threadIdx.x;
    float v = ent[i * 64 + (j & 63)] + h[i * 128 + j];
    float s = wsum(v * v);
    __shared__ float sm[4];
    if ((j & 31) == 0) sm[j >> 5] = s;
    __syncthreads();
    float tot = sm[0] + sm[1] + sm[2] + sm[3];
    out[i * 128 + j] = v / fmaxf(sqrtf(tot), kEPS);
}

// ------------------------- host orchestration -------------------------
namespace {
struct Ptrs {
    float *xn, *uA, *vA, *uB, *vB, *accA, *accB, *salA, *salB, *h, *ent, *wA, *wB;
    float *auA, *avA, *auB, *avB, *awA, *awB, *ebA, *ebB, *denA, *denB, *q;
};

static void get_ptrs(Ptrs& p) {
    cudaGetSymbolAddress((void**)&p.xn, d_xn);
    cudaGetSymbolAddress((void**)&p.uA, d_uA);
    cudaGetSymbolAddress((void**)&p.vA, d_vA);
    cudaGetSymbolAddress((void**)&p.uB, d_uB);
    cudaGetSymbolAddress((void**)&p.vB, d_vB);
    cudaGetSymbolAddress((void**)&p.accA, d_accA);
    cudaGetSymbolAddress((void**)&p.accB, d_accB);
    cudaGetSymbolAddress((void**)&p.salA, d_salA);
    cudaGetSymbolAddress((void**)&p.salB, d_salB);
    cudaGetSymbolAddress((void**)&p.h, d_h);
    cudaGetSymbolAddress((void**)&p.ent, d_ent);
    cudaGetSymbolAddress((void**)&p.wA, d_wA);
    cudaGetSymbolAddress((void**)&p.wB, d_wB);
    cudaGetSymbolAddress((void**)&p.auA, d_auA);
    cudaGetSymbolAddress((void**)&p.avA, d_avA);
    cudaGetSymbolAddress((void**)&p.auB, d_auB);
    cudaGetSymbolAddress((void**)&p.avB, d_avB);
    cudaGetSymbolAddress((void**)&p.awA, d_awA);
    cudaGetSymbolAddress((void**)&p.awB, d_awB);
    cudaGetSymbolAddress((void**)&p.ebA, d_ebA);
    cudaGetSymbolAddress((void**)&p.ebB, d_ebB);
    cudaGetSymbolAddress((void**)&p.denA, d_denA);
    cudaGetSymbolAddress((void**)&p.denB, d_denB);
    cudaGetSymbolAddress((void**)&p.q, d_q);
}

static void run_layer(const Ptrs& p,
                      const float* A, int lda, int K, int ldw,
                      const float* Wi, const float* bi, const float* ai,
                      const float* Wo, const float* bo, const float* ao,
                      const float* g,
                      const int* rowp, const int* colp, const int* et,
                      float* outH)
{
    // node projections (4 fused) on tensor cores
    dim3 gg((NN + 127) / 128, 4);
    gemm4_tc<<<gg, 256>>>(A, lda, K, Wi, Wo, ldw, p.uA, p.vA, p.uB, p.vB, NN);
    // attention q-vectors + au/av in one pass over A
    qprep<<<8, 128>>>(Wi, Wo, ldw, K, ai, ao, p.q);
    auav<<<(NN + 7) / 8, 256>>>(A, lda, K, p.q, p.auA, p.avA, p.auB, p.avB, NN);
    // relation projections + aw (both directions, one launch)
    dim3 gr(RR, 2);
    relproj2<<<gr, 128>>>(g, Wi, bi, ai, Wo, bo, ao, ldw, 2 * K,
                          p.wA, p.wB, p.awA, p.awB);
    // zero accumulators
    cudaMemsetAsync(p.accA, 0, NN * 128 * sizeof(float));
    cudaMemsetAsync(p.accB, 0, NN * 128 * sizeof(float));
    cudaMemsetAsync(p.salA, 0, NN * 2 * sizeof(float));
    cudaMemsetAsync(p.salB, 0, NN * 2 * sizeof(float));
    cudaMemsetAsync(p.denA, 0, NN * 2 * sizeof(float));
    cudaMemsetAsync(p.denB, 0, NN * 2 * sizeof(float));
    // edge passes (both directions fused)
    pass_a2<<<(EE + 255) / 256, 256>>>(rowp, colp, et,
                                       p.auA, p.avA, p.awA, p.auB, p.avB, p.awB,
                                       p.ebA, p.ebB, p.denA, p.denB);
    pass_b2<<<(EE + 7) / 8, 256>>>(rowp, colp, et, p.uA, p.wA, p.uB, p.wB,
                                   p.ebA, p.denA, p.ebB, p.denB,
                                   p.accA, p.salA, p.accB, p.salB);
    combine<<<NN, 128>>>(p.accA, p.salA, p.vA, p.accB, p.salB, p.vB, outH);
}
}  // namespace

extern "C" void kernel_launch(void* const* d_in, const int* in_sizes, int n_in,
                              void* d_out, int out_size)
{
    const float* x   = (const float*)d_in[0];
    const float* g   = (const float*)d_in[1];
    const int*   ei  = (const int*)d_in[2];
    const int*   et  = (const int*)d_in[3];
    const float* W1i = (const float*)d_in[4];
    const float* b1i = (const float*)d_in[5];
    const float* a1i = (const float*)d_in[6];
    const float* W1o = (const float*)d_in[7];
    const float* b1o = (const float*)d_in[8];
    const float* a1o = (const float*)d_in[9];
    const float* W2i = (const float*)d_in[10];
    const float* b2i = (const float*)d_in[11];
    const float* a2i = (const float*)d_in[12];
    const float* W2o = (const float*)d_in[13];
    const float* b2o = (const float*)d_in[14];
    const float* a2o = (const float*)d_in[15];
    const float* We  = (const float*)d_in[16];
    const float* be  = (const float*)d_in[17];
    const float* Wr  = (const float*)d_in[18];
    const float* br  = (const float*)d_in[19];
    float* out = (float*)d_out;

    const int* rowp = ei;
    const int* colp = ei + EE;

    Ptrs p;
    get_ptrs(p);

    norm_x<<<NN, 128>>>(x, p.xn);

    // layer 1: input xn [NN,100], d1 = 300
    run_layer(p, p.xn, XS, XS, 2 * XS + GS,
              W1i, b1i, a1i, W1o, b1o, a1o, g, rowp, colp, et, p.h);

    // layer 2: input h [NN,128], d2 = 356
    run_layer(p, p.h, 128, 128, 2 * 128 + GS,
              W2i, b2i, a2i, W2o, b2o, a2o, g, rowp, colp, et, p.h);

    // entity layer: ent = xn @ We.T + be  [NN,64]
    dim3 ge((NN + 63) / 64, 1);
    gemm_wt<<<ge, 256>>>(p.xn, XS, We, XS, XS, be, p.ent, 64, NN);

    // h_prime -> out[0 : NN*128)
    final_k<<<NN, 128>>>(p.ent, p.h, out);

    // g_prime -> out[NN*128 : NN*128 + RR*128)
    relproj_out<<<RR, 128>>>(g, Wr, br, out + NN * 128);
}

// round 5
// speedup vs baseline: 1.0281x; 1.0281x over previous
#include <cuda_runtime.h>
#include <math.h>
#include <stdint.h>

#define NN 50000
#define EE 400000
#define RR 500
#define XS 100
#define GS 100

static __device__ __constant__ float kNEG = 0.01f;
static __device__ __constant__ float kEPS = 1e-12f;

// ------------------------- scratch (device globals) -------------------------
__device__ float d_xn[NN * XS];
__device__ float d_uA[NN * 128];
__device__ float d_vA[NN * 128];
__device__ float d_uB[NN * 128];
__device__ float d_vB[NN * 128];
__device__ float d_accA[NN * 128];
__device__ float d_accB[NN * 128];
__device__ float d_salA[NN * 2];
__device__ float d_salB[NN * 2];
__device__ float d_h[NN * 128];
__device__ float d_ent[NN * 64];
__device__ float d_wA[RR * 128];
__device__ float d_wB[RR * 128];
__device__ float d_auA[NN * 2];
__device__ float d_avA[NN * 2];
__device__ float d_auB[NN * 2];
__device__ float d_avB[NN * 2];
__device__ float d_awA[RR * 2];
__device__ float d_awB[RR * 2];
__device__ float d_ebA[EE * 2];
__device__ float d_ebB[EE * 2];
__device__ float d_denA[NN * 2];
__device__ float d_denB[NN * 2];

// ------------------------- helpers -------------------------
__device__ __forceinline__ float wsum(float v) {
#pragma unroll
    for (int o = 16; o > 0; o >>= 1) v += __shfl_xor_sync(0xffffffffu, v, o);
    return v;
}

// L2-normalize rows of x [NN, XS]; blockDim = 128, one block per row
__global__ void norm_x(const float* __restrict__ x, float* __restrict__ xn) {
    int i = blockIdx.x;
    int j = threadIdx.x;
    float v = (j < XS) ? x[i * XS + j] : 0.f;
    float s = wsum(v * v);
    __shared__ float sm[4];
    if ((j & 31) == 0) sm[j >> 5] = s;
    __syncthreads();
    float tot = sm[0] + sm[1] + sm[2] + sm[3];
    if (j < XS) xn[i * XS + j] = v / fmaxf(sqrtf(tot), kEPS);
}

// Fused 4-projection GEMM + fused att-dot epilogue.
// y=0..3 computes C_y[M x 128] = A @ Wsel[:, koff:koff+K].T, and
// S_y[m,h] = sum_c att[h*64+c] * C_y[m, h*64+c] via atomics (S_y pre-zeroed).
// 128x128 block tile, 256 threads, 8x8 micro-tile, reg-prefetch pipeline.
__global__ __launch_bounds__(256) void gemm4(
    const float* __restrict__ A, int lda, int K,
    const float* __restrict__ Wi, const float* __restrict__ Wo, int ldw,
    const float* __restrict__ ai, const float* __restrict__ ao,
    float* __restrict__ uA, float* __restrict__ vA,
    float* __restrict__ uB, float* __restrict__ vB,
    float* __restrict__ auA, float* __restrict__ avA,
    float* __restrict__ auB, float* __restrict__ avB, int M)
{
    int y = blockIdx.y;
    const float* W = (y < 2) ? Wi : Wo;
    const float* att = (y < 2) ? ai : ao;
    int koff = (y & 1) ? K : 0;
    float* C = (y == 0) ? uA : (y == 1) ? vA : (y == 2) ? uB : vB;
    float* S = (y == 0) ? auA : (y == 1) ? avA : (y == 2) ? auB : avB;

    __shared__ float As[16][132];   // [k][m]
    __shared__ float Bs[16][132];   // [k][n]
    int m0 = blockIdx.x * 128;
    int tx = threadIdx.x & 15;      // n: tx*8
    int ty = threadIdx.x >> 4;      // m: ty*8
    float acc[8][8] = {};

    int lrow = threadIdx.x >> 1;
    int lkb = (threadIdx.x & 1) * 8;
    int gmA = m0 + lrow;
    const float* aBase = A + (size_t)gmA * lda;
    const float* wBase = W + (size_t)lrow * ldw + koff;
    bool rokA = (gmA < M);

    float ra[8], rb[8];
    // prologue: tile 0 into regs
#pragma unroll
    for (int i = 0; i < 8; i++) {
        int gk = lkb + i;
        ra[i] = (rokA && gk < K) ? aBase[gk] : 0.f;
        rb[i] = (gk < K) ? wBase[gk] : 0.f;
    }

    for (int k0 = 0; k0 < K; k0 += 16) {
        // commit regs to smem
#pragma unroll
        for (int i = 0; i < 8; i++) {
            As[lkb + i][lrow] = ra[i];
            Bs[lkb + i][lrow] = rb[i];
        }
        __syncthreads();
        // prefetch next tile into regs (overlaps compute)
        int kn = k0 + 16;
        if (kn < K) {
#pragma unroll
            for (int i = 0; i < 8; i++) {
                int gk = kn + lkb + i;
                ra[i] = (rokA && gk < K) ? aBase[gk] : 0.f;
                rb[i] = (gk < K) ? wBase[gk] : 0.f;
            }
        }
#pragma unroll
        for (int k = 0; k < 16; k++) {
            float4 a0 = *(const float4*)&As[k][ty * 8];
            float4 a1 = *(const float4*)&As[k][ty * 8 + 4];
            float4 b0 = *(const float4*)&Bs[k][tx * 8];
            float4 b1 = *(const float4*)&Bs[k][tx * 8 + 4];
            float av[8] = {a0.x, a0.y, a0.z, a0.w, a1.x, a1.y, a1.z, a1.w};
            float bv[8] = {b0.x, b0.y, b0.z, b0.w, b1.x, b1.y, b1.z, b1.w};
#pragma unroll
            for (int i = 0; i < 8; i++)
#pragma unroll
                for (int j = 0; j < 8; j++)
                    acc[i][j] = fmaf(av[i], bv[j], acc[i][j]);
        }
        __syncthreads();
    }

    // store C tile
#pragma unroll
    for (int i = 0; i < 8; i++) {
        int gm = m0 + ty * 8 + i;
        if (gm >= M) continue;
#pragma unroll
        for (int j = 0; j < 8; j += 4) {
            float4 v = make_float4(acc[i][j], acc[i][j + 1], acc[i][j + 2], acc[i][j + 3]);
            *(float4*)&C[(size_t)gm * 128 + tx * 8 + j] = v;
        }
    }

    // fused att-dot: S[m, h] += sum over this thread's 8 columns of att[col]*val,
    // reduced across the 16 tx-threads sharing a row via shfl (tx = lane&15).
    // Columns tx*8..tx*8+7 lie entirely in head h = tx>>3.
    int h = tx >> 3;
    float attv[8];
#pragma unroll
    for (int j = 0; j < 8; j++) attv[j] = att[tx * 8 + j];
#pragma unroll
    for (int i = 0; i < 8; i++) {
        float pp = 0.f;
#pragma unroll
        for (int j = 0; j < 8; j++) pp = fmaf(attv[j], acc[i][j], pp);
        // reduce over tx within each head-half: tx 0..7 (head0) and 8..15 (head1)
#pragma unroll
        for (int o = 1; o < 8; o <<= 1) pp += __shfl_xor_sync(0xffffffffu, pp, o);
        int gm = m0 + ty * 8 + i;
        if ((tx & 7) == 0 && gm < M)
            atomicAdd(&S[gm * 2 + h], pp);
    }
}

// C[M x N] = A[M x K] @ W.T (+bias) — entity layer
__global__ __launch_bounds__(256) void gemm_wt(
    const float* __restrict__ A, int lda,
    const float* __restrict__ W, int ldw, int K,
    const float* __restrict__ bias,
    float* __restrict__ C, int ldc, int M)
{
    __shared__ float As[64][17];
    __shared__ float Bs[16][65];
    int m0 = blockIdx.x * 64, n0 = blockIdx.y * 64;
    int tx = threadIdx.x & 15, ty = threadIdx.x >> 4;
    float acc[4][4] = {};
    for (int k0 = 0; k0 < K; k0 += 16) {
#pragma unroll
        for (int i = 0; i < 4; i++) {
            int li = threadIdx.x + i * 256;
            int k = li & 15, m = li >> 4;
            int gm = m0 + m, gk = k0 + k;
            As[m][k] = (gm < M && gk < K) ? A[gm * lda + gk] : 0.f;
        }
#pragma unroll
        for (int i = 0; i < 4; i++) {
            int li = threadIdx.x + i * 256;
            int k = li & 15, n = li >> 4;
            int gk = k0 + k;
            Bs[k][n] = (gk < K) ? W[(n0 + n) * ldw + gk] : 0.f;
        }
        __syncthreads();
#pragma unroll
        for (int k = 0; k < 16; k++) {
            float a[4], b[4];
#pragma unroll
            for (int i = 0; i < 4; i++) a[i] = As[ty * 4 + i][k];
#pragma unroll
            for (int j = 0; j < 4; j++) b[j] = Bs[k][tx * 4 + j];
#pragma unroll
            for (int i = 0; i < 4; i++)
#pragma unroll
                for (int j = 0; j < 4; j++)
                    acc[i][j] = fmaf(a[i], b[j], acc[i][j]);
        }
        __syncthreads();
    }
#pragma unroll
    for (int i = 0; i < 4; i++) {
        int gm = m0 + ty * 4 + i;
        if (gm >= M) continue;
#pragma unroll
        for (int j = 0; j < 4; j++) {
            int gn = n0 + tx * 4 + j;
            C[gm * ldc + gn] = acc[i][j] + bias[gn];
        }
    }
}

// Relation projection for both directions + fused aw reduction.
__global__ void relproj2(const float* __restrict__ g,
                         const float* __restrict__ Wi, const float* __restrict__ bi,
                         const float* __restrict__ ai,
                         const float* __restrict__ Wo, const float* __restrict__ bo,
                         const float* __restrict__ ao,
                         int ldw, int koff,
                         float* __restrict__ wA, float* __restrict__ wB,
                         float* __restrict__ awA, float* __restrict__ awB)
{
    int r = blockIdx.x, y = blockIdx.y;
    const float* W = y ? Wo : Wi;
    const float* b = y ? bo : bi;
    const float* att = y ? ao : ai;
    float* wout = y ? wB : wA;
    float* awout = y ? awB : awA;
    __shared__ float gs[GS];
    int n = threadIdx.x;
    if (n < GS) gs[n] = g[r * GS + n];
    __syncthreads();
    float acc = b[n];
    const float* wr = W + n * ldw + koff;
#pragma unroll 4
    for (int k = 0; k < GS; k++) acc = fmaf(wr[k], gs[k], acc);
    wout[r * 128 + n] = acc;
    float s = wsum(acc * att[n]);
    __shared__ float sm[4];
    if ((n & 31) == 0) sm[n >> 5] = s;
    __syncthreads();
    if (n == 0) awout[r * 2 + 0] = sm[0] + sm[1];
    if (n == 64) awout[r * 2 + 1] = sm[2] + sm[3];
}

// g_prime: block per relation
__global__ void relproj_out(const float* __restrict__ g, const float* __restrict__ Wr,
                            const float* __restrict__ br, float* __restrict__ out)
{
    int r = blockIdx.x;
    __shared__ float gs[GS];
    int n = threadIdx.x;
    if (n < GS) gs[n] = g[r * GS + n];
    __syncthreads();
    float acc = br[n];
    const float* wr = Wr + n * GS;
#pragma unroll 4
    for (int k = 0; k < GS; k++) acc = fmaf(wr[k], gs[k], acc);
    out[r * 128 + n] = acc;
}

// Fused pass A for both directions: one thread per edge.
__global__ __launch_bounds__(256) void pass_a2(
    const int* __restrict__ rowp, const int* __restrict__ colp, const int* __restrict__ et,
    const float* __restrict__ auA, const float* __restrict__ avA, const float* __restrict__ awA,
    const float* __restrict__ auB, const float* __restrict__ avB, const float* __restrict__ awB,
    float* __restrict__ ebA, float* __restrict__ ebB,
    float* __restrict__ denA, float* __restrict__ denB)
{
    int e = blockIdx.x * blockDim.x + threadIdx.x;
    if (e >= EE) return;
    int r = rowp[e], c = colp[e], t = et[e];
#pragma unroll
    for (int h = 0; h < 2; h++) {
        float a = auA[r * 2 + h] + avA[c * 2 + h] + awA[t * 2 + h];
        a = (a > 0.f) ? a : kNEG * a;
        float ex = expf(a);
        ebA[e * 2 + h] = ex;
        atomicAdd(&denA[r * 2 + h], ex);
        float b = auB[c * 2 + h] + avB[r * 2 + h] + awB[t * 2 + h];
        b = (b > 0.f) ? b : kNEG * b;
        float exb = expf(b);
        ebB[e * 2 + h] = exb;
        atomicAdd(&denB[c * 2 + h], exb);
    }
}

// Fused pass B for both directions: warp per edge.
__global__ __launch_bounds__(256) void pass_b2(
    const int* __restrict__ rowp, const int* __restrict__ colp, const int* __restrict__ et,
    const float* __restrict__ uA, const float* __restrict__ wA,
    const float* __restrict__ uB, const float* __restrict__ wB,
    const float* __restrict__ ebA, const float* __restrict__ denA,
    const float* __restrict__ ebB, const float* __restrict__ denB,
    float* __restrict__ accA, float* __restrict__ salA,
    float* __restrict__ accB, float* __restrict__ salB)
{
    int e = blockIdx.x * 8 + (threadIdx.x >> 5);
    if (e >= EE) return;
    int l = threadIdx.x & 31;
    int r = rowp[e], c = colp[e], t = et[e];
    int h = l >> 4;
    float aA = ebA[e * 2 + h] / denA[r * 2 + h];
    float aB = ebB[e * 2 + h] / denB[c * 2 + h];

    {
        float4 uv = ((const float4*)(uA + (size_t)r * 128))[l];
        float4 wv = ((const float4*)(wA + (size_t)t * 128))[l];
        float4 o;
        o.x = aA * (uv.x + wv.x); o.y = aA * (uv.y + wv.y);
        o.z = aA * (uv.z + wv.z); o.w = aA * (uv.w + wv.w);
        float* dst = accA + (size_t)c * 128 + l * 4;
        asm volatile("red.global.add.v4.f32 [%0], {%1, %2, %3, %4};"
                     :: "l"(dst), "f"(o.x), "f"(o.y), "f"(o.z), "f"(o.w) : "memory");
    }
    {
        float4 uv = ((const float4*)(uB + (size_t)c * 128))[l];
        float4 wv = ((const float4*)(wB + (size_t)t * 128))[l];
        float4 o;
        o.x = aB * (uv.x + wv.x); o.y = aB * (uv.y + wv.y);
        o.z = aB * (uv.z + wv.z); o.w = aB * (uv.w + wv.w);
        float* dst = accB + (size_t)r * 128 + l * 4;
        asm volatile("red.global.add.v4.f32 [%0], {%1, %2, %3, %4};"
                     :: "l"(dst), "f"(o.x), "f"(o.y), "f"(o.z), "f"(o.w) : "memory");
    }
    if (l == 0)  { atomicAdd(&salA[c * 2 + 0], aA); atomicAdd(&salB[r * 2 + 0], aB); }
    if (l == 16) { atomicAdd(&salA[c * 2 + 1], aA); atomicAdd(&salB[r * 2 + 1], aB); }
}

// out = l2norm_per_head(leaky(0.5*(accA + salA*vA) + 0.5*(accB + salB*vB)))
__global__ void combine(const float* __restrict__ accA, const float* __restrict__ salA,
                        const float* __restrict__ vA,
                        const float* __restrict__ accB, const float* __restrict__ salB,
                        const float* __restrict__ vB,
                        float* __restrict__ out)
{
    int i = blockIdx.x, j = threadIdx.x;
    int h = j >> 6;
    float a = accA[i * 128 + j] + salA[i * 2 + h] * vA[i * 128 + j];
    float b = accB[i * 128 + j] + salB[i * 2 + h] * vB[i * 128 + j];
    float v = 0.5f * (a + b);
    v = (v > 0.f) ? v : kNEG * v;
    float s = wsum(v * v);
    __shared__ float sm[4];
    if ((j & 31) == 0) sm[j >> 5] = s;
    __syncthreads();
    float tot = sm[h * 2] + sm[h * 2 + 1];
    out[i * 128 + j] = v / fmaxf(sqrtf(tot), kEPS);
}

// h_prime = l2norm_128(ent broadcast over heads + h)
__global__ void final_k(const float* __restrict__ ent, const float* __restrict__ h,
                        float* __restrict__ out)
{
    int i = blockIdx.x, j = threadIdx.x;
    float v = ent[i * 64 + (j & 63)] + h[i * 128 + j];
    float s = wsum(v * v);
    __shared__ float sm[4];
    if ((j & 31) == 0) sm[j >> 5] = s;
    __syncthreads();
    float tot = sm[0] + sm[1] + sm[2] + sm[3];
    out[i * 128 + j] = v / fmaxf(sqrtf(tot), kEPS);
}

// ------------------------- host orchestration -------------------------
namespace {
struct Ptrs {
    float *xn, *uA, *vA, *uB, *vB, *accA, *accB, *salA, *salB, *h, *ent, *wA, *wB;
    float *auA, *avA, *auB, *avB, *awA, *awB, *ebA, *ebB, *denA, *denB;
};

static void get_ptrs(Ptrs& p) {
    cudaGetSymbolAddress((void**)&p.xn, d_xn);
    cudaGetSymbolAddress((void**)&p.uA, d_uA);
    cudaGetSymbolAddress((void**)&p.vA, d_vA);
    cudaGetSymbolAddress((void**)&p.uB, d_uB);
    cudaGetSymbolAddress((void**)&p.vB, d_vB);
    cudaGetSymbolAddress((void**)&p.accA, d_accA);
    cudaGetSymbolAddress((void**)&p.accB, d_accB);
    cudaGetSymbolAddress((void**)&p.salA, d_salA);
    cudaGetSymbolAddress((void**)&p.salB, d_salB);
    cudaGetSymbolAddress((void**)&p.h, d_h);
    cudaGetSymbolAddress((void**)&p.ent, d_ent);
    cudaGetSymbolAddress((void**)&p.wA, d_wA);
    cudaGetSymbolAddress((void**)&p.wB, d_wB);
    cudaGetSymbolAddress((void**)&p.auA, d_auA);
    cudaGetSymbolAddress((void**)&p.avA, d_avA);
    cudaGetSymbolAddress((void**)&p.auB, d_auB);
    cudaGetSymbolAddress((void**)&p.avB, d_avB);
    cudaGetSymbolAddress((void**)&p.awA, d_awA);
    cudaGetSymbolAddress((void**)&p.awB, d_awB);
    cudaGetSymbolAddress((void**)&p.ebA, d_ebA);
    cudaGetSymbolAddress((void**)&p.ebB, d_ebB);
    cudaGetSymbolAddress((void**)&p.denA, d_denA);
    cudaGetSymbolAddress((void**)&p.denB, d_denB);
}

static void run_layer(const Ptrs& p,
                      const float* A, int lda, int K, int ldw,
                      const float* Wi, const float* bi, const float* ai,
                      const float* Wo, const float* bo, const float* ao,
                      const float* g,
                      const int* rowp, const int* colp, const int* et,
                      float* outH)
{
    // zero the att-scalar accumulators before gemm4's fused epilogue
    cudaMemsetAsync(p.auA, 0, NN * 2 * sizeof(float));
    cudaMemsetAsync(p.avA, 0, NN * 2 * sizeof(float));
    cudaMemsetAsync(p.auB, 0, NN * 2 * sizeof(float));
    cudaMemsetAsync(p.avB, 0, NN * 2 * sizeof(float));
    // node projections (4 fused) + fused att-dot epilogue
    dim3 gg((NN + 127) / 128, 4);
    gemm4<<<gg, 256>>>(A, lda, K, Wi, Wo, ldw, ai, ao,
                       p.uA, p.vA, p.uB, p.vB,
                       p.auA, p.avA, p.auB, p.avB, NN);
    // relation projections + aw (both directions, one launch)
    dim3 gr(RR, 2);
    relproj2<<<gr, 128>>>(g, Wi, bi, ai, Wo, bo, ao, ldw, 2 * K,
                          p.wA, p.wB, p.awA, p.awB);
    // zero accumulators
    cudaMemsetAsync(p.accA, 0, NN * 128 * sizeof(float));
    cudaMemsetAsync(p.accB, 0, NN * 128 * sizeof(float));
    cudaMemsetAsync(p.salA, 0, NN * 2 * sizeof(float));
    cudaMemsetAsync(p.salB, 0, NN * 2 * sizeof(float));
    cudaMemsetAsync(p.denA, 0, NN * 2 * sizeof(float));
    cudaMemsetAsync(p.denB, 0, NN * 2 * sizeof(float));
    // edge passes (both directions fused)
    pass_a2<<<(EE + 255) / 256, 256>>>(rowp, colp, et,
                                       p.auA, p.avA, p.awA, p.auB, p.avB, p.awB,
                                       p.ebA, p.ebB, p.denA, p.denB);
    pass_b2<<<(EE + 7) / 8, 256>>>(rowp, colp, et, p.uA, p.wA, p.uB, p.wB,
                                   p.ebA, p.denA, p.ebB, p.denB,
                                   p.accA, p.salA, p.accB, p.salB);
    combine<<<NN, 128>>>(p.accA, p.salA, p.vA, p.accB, p.salB, p.vB, outH);
}
}  // namespace

extern "C" void kernel_launch(void* const* d_in, const int* in_sizes, int n_in,
                              void* d_out, int out_size)
{
    const float* x   = (const float*)d_in[0];
    const float* g   = (const float*)d_in[1];
    const int*   ei  = (const int*)d_in[2];
    const int*   et  = (const int*)d_in[3];
    const float* W1i = (const float*)d_in[4];
    const float* b1i = (const float*)d_in[5];
    const float* a1i = (const float*)d_in[6];
    const float* W1o = (const float*)d_in[7];
    const float* b1o = (const float*)d_in[8];
    const float* a1o = (const float*)d_in[9];
    const float* W2i = (const float*)d_in[10];
    const float* b2i = (const float*)d_in[11];
    const float* a2i = (const float*)d_in[12];
    const float* W2o = (const float*)d_in[13];
    const float* b2o = (const float*)d_in[14];
    const float* a2o = (const float*)d_in[15];
    const float* We  = (const float*)d_in[16];
    const float* be  = (const float*)d_in[17];
    const float* Wr  = (const float*)d_in[18];
    const float* br  = (const float*)d_in[19];
    float* out = (float*)d_out;

    const int* rowp = ei;
    const int* colp = ei + EE;

    Ptrs p;
    get_ptrs(p);

    norm_x<<<NN, 128>>>(x, p.xn);

    // layer 1: input xn [NN,100], d1 = 300
    run_layer(p, p.xn, XS, XS, 2 * XS + GS,
              W1i, b1i, a1i, W1o, b1o, a1o, g, rowp, colp, et, p.h);

    // layer 2: input h [NN,128], d2 = 356
    run_layer(p, p.h, 128, 128, 2 * 128 + GS,
              W2i, b2i, a2i, W2o, b2o, a2o, g, rowp, colp, et, p.h);

    // entity layer: ent = xn @ We.T + be  [NN,64]
    dim3 ge((NN + 63) / 64, 1);
    gemm_wt<<<ge, 256>>>(p.xn, XS, We, XS, XS, be, p.ent, 64, NN);

    // h_prime -> out[0 : NN*128)
    final_k<<<NN, 128>>>(p.ent, p.h, out);

    // g_prime -> out[NN*128 : NN*128 + RR*128)
    relproj_out<<<RR, 128>>>(g, Wr, br, out + NN * 128);
}

// round 6
// speedup vs baseline: 1.0649x; 1.0357x over previous
#include <cuda_runtime.h>
#include <math.h>
#include <stdint.h>

#define NN 50000
#define EE 400000
#define RR 500
#define XS 100
#define GS 100

static __device__ __constant__ float kNEG = 0.01f;
static __device__ __constant__ float kEPS = 1e-12f;

// ------------------------- scratch (device globals) -------------------------
__device__ float d_xn[NN * XS];
__device__ float d_uA[NN * 128];
__device__ float d_vA[NN * 128];
__device__ float d_uB[NN * 128];
__device__ float d_vB[NN * 128];
__device__ float d_accA[NN * 128];
__device__ float d_accB[NN * 128];
__device__ float d_salA[NN * 2];
__device__ float d_salB[NN * 2];
__device__ float d_h[NN * 128];
__device__ float d_ent[NN * 64];
__device__ float d_wA[RR * 128];
__device__ float d_wB[RR * 128];
__device__ float d_psc[NN * 8];   // per-node packed: auA0,auA1,avA0,avA1,auB0,auB1,avB0,avB1
__device__ float d_paw[RR * 4];   // per-rel packed:  awA0,awA1,awB0,awB1
__device__ float d_ebA[EE * 2];
__device__ float d_ebB[EE * 2];
__device__ float d_denA[NN * 2];
__device__ float d_denB[NN * 2];

// ------------------------- helpers -------------------------
__device__ __forceinline__ float wsum(float v) {
#pragma unroll
    for (int o = 16; o > 0; o >>= 1) v += __shfl_xor_sync(0xffffffffu, v, o);
    return v;
}

// L2-normalize rows of x [NN, XS]; blockDim = 128, one block per row
__global__ void norm_x(const float* __restrict__ x, float* __restrict__ xn) {
    int i = blockIdx.x;
    int j = threadIdx.x;
    float v = (j < XS) ? x[i * XS + j] : 0.f;
    float s = wsum(v * v);
    __shared__ float sm[4];
    if ((j & 31) == 0) sm[j >> 5] = s;
    __syncthreads();
    float tot = sm[0] + sm[1] + sm[2] + sm[3];
    if (j < XS) xn[i * XS + j] = v / fmaxf(sqrtf(tot), kEPS);
}

// Fused 4-projection GEMM + fused att-dot epilogue.
// y=0..3: C_y[M x 128] = A @ Wsel[:, koff:koff+K].T, and
// psc[m*8 + y*2 + h] += sum_c att[h*64+c] * C_y[m, h*64+c]  (psc pre-zeroed).
// 128x128 block tile, 256 threads, 8x8 micro-tile.
__global__ __launch_bounds__(256) void gemm4(
    const float* __restrict__ A, int lda, int K,
    const float* __restrict__ Wi, const float* __restrict__ Wo, int ldw,
    const float* __restrict__ ai, const float* __restrict__ ao,
    float* __restrict__ uA, float* __restrict__ vA,
    float* __restrict__ uB, float* __restrict__ vB,
    float* __restrict__ psc, int M)
{
    int y = blockIdx.y;
    const float* W = (y < 2) ? Wi : Wo;
    const float* att = (y < 2) ? ai : ao;
    int koff = (y & 1) ? K : 0;
    float* C = (y == 0) ? uA : (y == 1) ? vA : (y == 2) ? uB : vB;

    __shared__ float As[16][132];   // [k][m]
    __shared__ float Bs[16][132];   // [k][n]
    int m0 = blockIdx.x * 128;
    int tx = threadIdx.x & 15;      // n: tx*8
    int ty = threadIdx.x >> 4;      // m: ty*8
    float acc[8][8] = {};

    for (int k0 = 0; k0 < K; k0 += 16) {
        {
            int m = threadIdx.x >> 1;
            int kb = (threadIdx.x & 1) * 8;
            int gm = m0 + m;
#pragma unroll
            for (int i = 0; i < 8; i++) {
                int gk = k0 + kb + i;
                As[kb + i][m] = (gm < M && gk < K) ? A[gm * lda + gk] : 0.f;
            }
        }
        {
            int n = threadIdx.x >> 1;
            int kb = (threadIdx.x & 1) * 8;
#pragma unroll
            for (int i = 0; i < 8; i++) {
                int gk = k0 + kb + i;
                Bs[kb + i][n] = (gk < K) ? W[n * ldw + koff + gk] : 0.f;
            }
        }
        __syncthreads();
#pragma unroll
        for (int k = 0; k < 16; k++) {
            float4 a0 = *(const float4*)&As[k][ty * 8];
            float4 a1 = *(const float4*)&As[k][ty * 8 + 4];
            float4 b0 = *(const float4*)&Bs[k][tx * 8];
            float4 b1 = *(const float4*)&Bs[k][tx * 8 + 4];
            float av[8] = {a0.x, a0.y, a0.z, a0.w, a1.x, a1.y, a1.z, a1.w};
            float bv[8] = {b0.x, b0.y, b0.z, b0.w, b1.x, b1.y, b1.z, b1.w};
#pragma unroll
            for (int i = 0; i < 8; i++)
#pragma unroll
                for (int j = 0; j < 8; j++)
                    acc[i][j] = fmaf(av[i], bv[j], acc[i][j]);
        }
        __syncthreads();
    }

    // store C tile
#pragma unroll
    for (int i = 0; i < 8; i++) {
        int gm = m0 + ty * 8 + i;
        if (gm >= M) continue;
#pragma unroll
        for (int j = 0; j < 8; j += 4) {
            float4 v = make_float4(acc[i][j], acc[i][j + 1], acc[i][j + 2], acc[i][j + 3]);
            *(float4*)&C[(size_t)gm * 128 + tx * 8 + j] = v;
        }
    }

    // fused att-dot epilogue: columns tx*8..tx*8+7 lie in head h = tx>>3.
    int h = tx >> 3;
    float attv[8];
#pragma unroll
    for (int j = 0; j < 8; j++) attv[j] = att[tx * 8 + j];
#pragma unroll
    for (int i = 0; i < 8; i++) {
        float pp = 0.f;
#pragma unroll
        for (int j = 0; j < 8; j++) pp = fmaf(attv[j], acc[i][j], pp);
#pragma unroll
        for (int o = 1; o < 8; o <<= 1) pp += __shfl_xor_sync(0xffffffffu, pp, o);
        int gm = m0 + ty * 8 + i;
        if ((tx & 7) == 0 && gm < M)
            atomicAdd(&psc[gm * 8 + y * 2 + h], pp);
    }
}

// C[M x N] = A[M x K] @ W.T (+bias) — entity layer
__global__ __launch_bounds__(256) void gemm_wt(
    const float* __restrict__ A, int lda,
    const float* __restrict__ W, int ldw, int K,
    const float* __restrict__ bias,
    float* __restrict__ C, int ldc, int M)
{
    __shared__ float As[64][17];
    __shared__ float Bs[16][65];
    int m0 = blockIdx.x * 64, n0 = blockIdx.y * 64;
    int tx = threadIdx.x & 15, ty = threadIdx.x >> 4;
    float acc[4][4] = {};
    for (int k0 = 0; k0 < K; k0 += 16) {
#pragma unroll
        for (int i = 0; i < 4; i++) {
            int li = threadIdx.x + i * 256;
            int k = li & 15, m = li >> 4;
            int gm = m0 + m, gk = k0 + k;
            As[m][k] = (gm < M && gk < K) ? A[gm * lda + gk] : 0.f;
        }
#pragma unroll
        for (int i = 0; i < 4; i++) {
            int li = threadIdx.x + i * 256;
            int k = li & 15, n = li >> 4;
            int gk = k0 + k;
            Bs[k][n] = (gk < K) ? W[(n0 + n) * ldw + gk] : 0.f;
        }
        __syncthreads();
#pragma unroll
        for (int k = 0; k < 16; k++) {
            float a[4], b[4];
#pragma unroll
            for (int i = 0; i < 4; i++) a[i] = As[ty * 4 + i][k];
#pragma unroll
            for (int j = 0; j < 4; j++) b[j] = Bs[k][tx * 4 + j];
#pragma unroll
            for (int i = 0; i < 4; i++)
#pragma unroll
                for (int j = 0; j < 4; j++)
                    acc[i][j] = fmaf(a[i], b[j], acc[i][j]);
        }
        __syncthreads();
    }
#pragma unroll
    for (int i = 0; i < 4; i++) {
        int gm = m0 + ty * 4 + i;
        if (gm >= M) continue;
#pragma unroll
        for (int j = 0; j < 4; j++) {
            int gn = n0 + tx * 4 + j;
            C[gm * ldc + gn] = acc[i][j] + bias[gn];
        }
    }
}

// Relation projection for both directions + fused aw reduction (packed output).
__global__ void relproj2(const float* __restrict__ g,
                         const float* __restrict__ Wi, const float* __restrict__ bi,
                         const float* __restrict__ ai,
                         const float* __restrict__ Wo, const float* __restrict__ bo,
                         const float* __restrict__ ao,
                         int ldw, int koff,
                         float* __restrict__ wA, float* __restrict__ wB,
                         float* __restrict__ paw)
{
    int r = blockIdx.x, y = blockIdx.y;
    const float* W = y ? Wo : Wi;
    const float* b = y ? bo : bi;
    const float* att = y ? ao : ai;
    float* wout = y ? wB : wA;
    __shared__ float gs[GS];
    int n = threadIdx.x;
    if (n < GS) gs[n] = g[r * GS + n];
    __syncthreads();
    float acc = b[n];
    const float* wr = W + n * ldw + koff;
#pragma unroll 4
    for (int k = 0; k < GS; k++) acc = fmaf(wr[k], gs[k], acc);
    wout[r * 128 + n] = acc;
    float s = wsum(acc * att[n]);
    __shared__ float sm[4];
    if ((n & 31) == 0) sm[n >> 5] = s;
    __syncthreads();
    if (n == 0) paw[r * 4 + y * 2 + 0] = sm[0] + sm[1];
    if (n == 64) paw[r * 4 + y * 2 + 1] = sm[2] + sm[3];
}

// g_prime: block per relation
__global__ void relproj_out(const float* __restrict__ g, const float* __restrict__ Wr,
                            const float* __restrict__ br, float* __restrict__ out)
{
    int r = blockIdx.x;
    __shared__ float gs[GS];
    int n = threadIdx.x;
    if (n < GS) gs[n] = g[r * GS + n];
    __syncthreads();
    float acc = br[n];
    const float* wr = Wr + n * GS;
#pragma unroll 4
    for (int k = 0; k < GS; k++) acc = fmaf(wr[k], gs[k], acc);
    out[r * 128 + n] = acc;
}

// Fused pass A for both directions: one thread per edge, packed-scalar gathers.
// psc[m*8+]: auA0,auA1,avA0,avA1,auB0,auB1,avB0,avB1; paw[t*4+]: awA0,awA1,awB0,awB1
__global__ __launch_bounds__(256) void pass_a2(
    const int* __restrict__ rowp, const int* __restrict__ colp, const int* __restrict__ et,
    const float* __restrict__ psc, const float* __restrict__ paw,
    float* __restrict__ ebA, float* __restrict__ ebB,
    float* __restrict__ denA, float* __restrict__ denB)
{
    int e = blockIdx.x * blockDim.x + threadIdx.x;
    if (e >= EE) return;
    int r = rowp[e], c = colp[e], t = et[e];
    float4 r0 = *(const float4*)&psc[r * 8];      // auA[r], avA[r]
    float4 r1 = *(const float4*)&psc[r * 8 + 4];  // auB[r], avB[r]
    float4 c0 = *(const float4*)&psc[c * 8];      // auA[c], avA[c]
    float4 c1 = *(const float4*)&psc[c * 8 + 4];  // auB[c], avB[c]
    float4 aw = *(const float4*)&paw[t * 4];      // awA, awB

    // dir A: au[r] + av[c] + awA
    float a0 = r0.x + c0.z + aw.x;
    float a1 = r0.y + c0.w + aw.y;
    // dir B: au[c] + av[r] + awB
    float b0 = c1.x + r1.z + aw.z;
    float b1 = c1.y + r1.w + aw.w;

    a0 = (a0 > 0.f) ? a0 : kNEG * a0;
    a1 = (a1 > 0.f) ? a1 : kNEG * a1;
    b0 = (b0 > 0.f) ? b0 : kNEG * b0;
    b1 = (b1 > 0.f) ? b1 : kNEG * b1;
    float ea0 = expf(a0), ea1 = expf(a1), eb0 = expf(b0), eb1 = expf(b1);
    *(float2*)&ebA[e * 2] = make_float2(ea0, ea1);
    *(float2*)&ebB[e * 2] = make_float2(eb0, eb1);
    atomicAdd(&denA[r * 2 + 0], ea0);
    atomicAdd(&denA[r * 2 + 1], ea1);
    atomicAdd(&denB[c * 2 + 0], eb0);
    atomicAdd(&denB[c * 2 + 1], eb1);
}

// Fused pass B for both directions: warp per edge.
__global__ __launch_bounds__(256) void pass_b2(
    const int* __restrict__ rowp, const int* __restrict__ colp, const int* __restrict__ et,
    const float* __restrict__ uA, const float* __restrict__ wA,
    const float* __restrict__ uB, const float* __restrict__ wB,
    const float* __restrict__ ebA, const float* __restrict__ denA,
    const float* __restrict__ ebB, const float* __restrict__ denB,
    float* __restrict__ accA, float* __restrict__ salA,
    float* __restrict__ accB, float* __restrict__ salB)
{
    int e = blockIdx.x * 8 + (threadIdx.x >> 5);
    if (e >= EE) return;
    int l = threadIdx.x & 31;
    int r = rowp[e], c = colp[e], t = et[e];
    int h = l >> 4;
    float aA = ebA[e * 2 + h] / denA[r * 2 + h];
    float aB = ebB[e * 2 + h] / denB[c * 2 + h];

    {
        float4 uv = ((const float4*)(uA + (size_t)r * 128))[l];
        float4 wv = ((const float4*)(wA + (size_t)t * 128))[l];
        float4 o;
        o.x = aA * (uv.x + wv.x); o.y = aA * (uv.y + wv.y);
        o.z = aA * (uv.z + wv.z); o.w = aA * (uv.w + wv.w);
        float* dst = accA + (size_t)c * 128 + l * 4;
        asm volatile("red.global.add.v4.f32 [%0], {%1, %2, %3, %4};"
                     :: "l"(dst), "f"(o.x), "f"(o.y), "f"(o.z), "f"(o.w) : "memory");
    }
    {
        float4 uv = ((const float4*)(uB + (size_t)c * 128))[l];
        float4 wv = ((const float4*)(wB + (size_t)t * 128))[l];
        float4 o;
        o.x = aB * (uv.x + wv.x); o.y = aB * (uv.y + wv.y);
        o.z = aB * (uv.z + wv.z); o.w = aB * (uv.w + wv.w);
        float* dst = accB + (size_t)r * 128 + l * 4;
        asm volatile("red.global.add.v4.f32 [%0], {%1, %2, %3, %4};"
                     :: "l"(dst), "f"(o.x), "f"(o.y), "f"(o.z), "f"(o.w) : "memory");
    }
    if (l == 0)  { atomicAdd(&salA[c * 2 + 0], aA); atomicAdd(&salB[r * 2 + 0], aB); }
    if (l == 16) { atomicAdd(&salA[c * 2 + 1], aA); atomicAdd(&salB[r * 2 + 1], aB); }
}

// out = l2norm_per_head(leaky(0.5*(accA + salA*vA) + 0.5*(accB + salB*vB)))
__global__ void combine(const float* __restrict__ accA, const float* __restrict__ salA,
                        const float* __restrict__ vA,
                        const float* __restrict__ accB, const float* __restrict__ salB,
                        const float* __restrict__ vB,
                        float* __restrict__ out)
{
    int i = blockIdx.x, j = threadIdx.x;
    int h = j >> 6;
    float a = accA[i * 128 + j] + salA[i * 2 + h] * vA[i * 128 + j];
    float b = accB[i * 128 + j] + salB[i * 2 + h] * vB[i * 128 + j];
    float v = 0.5f * (a + b);
    v = (v > 0.f) ? v : kNEG * v;
    float s = wsum(v * v);
    __shared__ float sm[4];
    if ((j & 31) == 0) sm[j >> 5] = s;
    __syncthreads();
    float tot = sm[h * 2] + sm[h * 2 + 1];
    out[i * 128 + j] = v / fmaxf(sqrtf(tot), kEPS);
}

// h_prime = l2norm_128(ent broadcast over heads + h)
__global__ void final_k(const float* __restrict__ ent, const float* __restrict__ h,
                        float* __restrict__ out)
{
    int i = blockIdx.x, j = threadIdx.x;
    float v = ent[i * 64 + (j & 63)] + h[i * 128 + j];
    float s = wsum(v * v);
    __shared__ float sm[4];
    if ((j & 31) == 0) sm[j >> 5] = s;
    __syncthreads();
    float tot = sm[0] + sm[1] + sm[2] + sm[3];
    out[i * 128 + j] = v / fmaxf(sqrtf(tot), kEPS);
}

// ------------------------- host orchestration -------------------------
namespace {
struct Ptrs {
    float *xn, *uA, *vA, *uB, *vB, *accA, *accB, *salA, *salB, *h, *ent, *wA, *wB;
    float *psc, *paw, *ebA, *ebB, *denA, *denB;
};

static void get_ptrs(Ptrs& p) {
    cudaGetSymbolAddress((void**)&p.xn, d_xn);
    cudaGetSymbolAddress((void**)&p.uA, d_uA);
    cudaGetSymbolAddress((void**)&p.vA, d_vA);
    cudaGetSymbolAddress((void**)&p.uB, d_uB);
    cudaGetSymbolAddress((void**)&p.vB, d_vB);
    cudaGetSymbolAddress((void**)&p.accA, d_accA);
    cudaGetSymbolAddress((void**)&p.accB, d_accB);
    cudaGetSymbolAddress((void**)&p.salA, d_salA);
    cudaGetSymbolAddress((void**)&p.salB, d_salB);
    cudaGetSymbolAddress((void**)&p.h, d_h);
    cudaGetSymbolAddress((void**)&p.ent, d_ent);
    cudaGetSymbolAddress((void**)&p.wA, d_wA);
    cudaGetSymbolAddress((void**)&p.wB, d_wB);
    cudaGetSymbolAddress((void**)&p.psc, d_psc);
    cudaGetSymbolAddress((void**)&p.paw, d_paw);
    cudaGetSymbolAddress((void**)&p.ebA, d_ebA);
    cudaGetSymbolAddress((void**)&p.ebB, d_ebB);
    cudaGetSymbolAddress((void**)&p.denA, d_denA);
    cudaGetSymbolAddress((void**)&p.denB, d_denB);
}

static void run_layer(const Ptrs& p,
                      const float* A, int lda, int K, int ldw,
                      const float* Wi, const float* bi, const float* ai,
                      const float* Wo, const float* bo, const float* ao,
                      const float* g,
                      const int* rowp, const int* colp, const int* et,
                      float* outH)
{
    // zero packed att-scalar accumulator before gemm4's fused epilogue
    cudaMemsetAsync(p.psc, 0, NN * 8 * sizeof(float));
    // node projections (4 fused) + fused att-dot epilogue
    dim3 gg((NN + 127) / 128, 4);
    gemm4<<<gg, 256>>>(A, lda, K, Wi, Wo, ldw, ai, ao,
                       p.uA, p.vA, p.uB, p.vB, p.psc, NN);
    // relation projections + packed aw (both directions, one launch)
    dim3 gr(RR, 2);
    relproj2<<<gr, 128>>>(g, Wi, bi, ai, Wo, bo, ao, ldw, 2 * K,
                          p.wA, p.wB, p.paw);
    // zero accumulators
    cudaMemsetAsync(p.accA, 0, NN * 128 * sizeof(float));
    cudaMemsetAsync(p.accB, 0, NN * 128 * sizeof(float));
    cudaMemsetAsync(p.salA, 0, NN * 2 * sizeof(float));
    cudaMemsetAsync(p.salB, 0, NN * 2 * sizeof(float));
    cudaMemsetAsync(p.denA, 0, NN * 2 * sizeof(float));
    cudaMemsetAsync(p.denB, 0, NN * 2 * sizeof(float));
    // edge passes (both directions fused)
    pass_a2<<<(EE + 255) / 256, 256>>>(rowp, colp, et, p.psc, p.paw,
                                       p.ebA, p.ebB, p.denA, p.denB);
    pass_b2<<<(EE + 7) / 8, 256>>>(rowp, colp, et, p.uA, p.wA, p.uB, p.wB,
                                   p.ebA, p.denA, p.ebB, p.denB,
                                   p.accA, p.salA, p.accB, p.salB);
    combine<<<NN, 128>>>(p.accA, p.salA, p.vA, p.accB, p.salB, p.vB, outH);
}
}  // namespace

extern "C" void kernel_launch(void* const* d_in, const int* in_sizes, int n_in,
                              void* d_out, int out_size)
{
    const float* x   = (const float*)d_in[0];
    const float* g   = (const float*)d_in[1];
    const int*   ei  = (const int*)d_in[2];
    const int*   et  = (const int*)d_in[3];
    const float* W1i = (const float*)d_in[4];
    const float* b1i = (const float*)d_in[5];
    const float* a1i = (const float*)d_in[6];
    const float* W1o = (const float*)d_in[7];
    const float* b1o = (const float*)d_in[8];
    const float* a1o = (const float*)d_in[9];
    const float* W2i = (const float*)d_in[10];
    const float* b2i = (const float*)d_in[11];
    const float* a2i = (const float*)d_in[12];
    const float* W2o = (const float*)d_in[13];
    const float* b2o = (const float*)d_in[14];
    const float* a2o = (const float*)d_in[15];
    const float* We  = (const float*)d_in[16];
    const float* be  = (const float*)d_in[17];
    const float* Wr  = (const float*)d_in[18];
    const float* br  = (const float*)d_in[19];
    float* out = (float*)d_out;

    const int* rowp = ei;
    const int* colp = ei + EE;

    Ptrs p;
    get_ptrs(p);

    norm_x<<<NN, 128>>>(x, p.xn);

    // layer 1: input xn [NN,100], d1 = 300
    run_layer(p, p.xn, XS, XS, 2 * XS + GS,
              W1i, b1i, a1i, W1o, b1o, a1o, g, rowp, colp, et, p.h);

    // layer 2: input h [NN,128], d2 = 356
    run_layer(p, p.h, 128, 128, 2 * 128 + GS,
              W2i, b2i, a2i, W2o, b2o, a2o, g, rowp, colp, et, p.h);

    // entity layer: ent = xn @ We.T + be  [NN,64]
    dim3 ge((NN + 63) / 64, 1);
    gemm_wt<<<ge, 256>>>(p.xn, XS, We, XS, XS, be, p.ent, 64, NN);

    // h_prime -> out[0 : NN*128)
    final_k<<<NN, 128>>>(p.ent, p.h, out);

    // g_prime -> out[NN*128 : NN*128 + RR*128)
    relproj_out<<<RR, 128>>>(g, Wr, br, out + NN * 128);
}

// round 7
// speedup vs baseline: 1.2253x; 1.1507x over previous
#include <cuda_runtime.h>
#include <math.h>
#include <stdint.h>

#define NN 50000
#define EE 400000
#define RR 500
#define XS 100
#define GS 100

static __device__ __constant__ float kNEG = 0.01f;
static __device__ __constant__ float kEPS = 1e-12f;

// ------------------------- scratch (device globals) -------------------------
__device__ float d_xn[NN * XS];
__device__ float d_At[128 * NN];        // k-major transposed activations (zero-padded to k=128)
__device__ float d_Wt[4 * 128 * 128];   // k-major weight slices per projection y
__device__ float d_uA[NN * 128];
__device__ float d_vA[NN * 128];
__device__ float d_uB[NN * 128];
__device__ float d_vB[NN * 128];
__device__ float d_accA[NN * 128];
__device__ float d_accB[NN * 128];
__device__ float d_salA[NN * 2];
__device__ float d_salB[NN * 2];
__device__ float d_h[NN * 128];
__device__ float d_ent[NN * 64];
__device__ float d_wA[RR * 128];
__device__ float d_wB[RR * 128];
__device__ float d_psc[NN * 8];   // packed per-node: auA0,auA1,avA0,avA1,auB0,auB1,avB0,avB1
__device__ float d_paw[RR * 4];   // packed per-rel:  awA0,awA1,awB0,awB1
__device__ float d_ebA[EE * 2];
__device__ float d_ebB[EE * 2];
__device__ float d_denA[NN * 2];
__device__ float d_denB[NN * 2];

// ------------------------- helpers -------------------------
__device__ __forceinline__ float wsum(float v) {
#pragma unroll
    for (int o = 16; o > 0; o >>= 1) v += __shfl_xor_sync(0xffffffffu, v, o);
    return v;
}

__device__ __forceinline__ uint32_t s2u(const void* p) {
    return (uint32_t)__cvta_generic_to_shared(p);
}

// L2-normalize rows of x [NN, XS]; blockDim = 128, one block per row
__global__ void norm_x(const float* __restrict__ x, float* __restrict__ xn) {
    int i = blockIdx.x;
    int j = threadIdx.x;
    float v = (j < XS) ? x[i * XS + j] : 0.f;
    float s = wsum(v * v);
    __shared__ float sm[4];
    if ((j & 31) == 0) sm[j >> 5] = s;
    __syncthreads();
    float tot = sm[0] + sm[1] + sm[2] + sm[3];
    if (j < XS) xn[i * XS + j] = v / fmaxf(sqrtf(tot), kEPS);
}

// At[k][m] = A[m][k], zero-padded rows k in [K, 128). grid (ceil(M/32), 4), block (32,8)
__global__ void transpose_A(const float* __restrict__ A, int M, int K,
                            float* __restrict__ At) {
    __shared__ float t[32][33];
    int mb = blockIdx.x * 32, kb = blockIdx.y * 32;
    int tx = threadIdx.x, ty = threadIdx.y;
#pragma unroll
    for (int i = 0; i < 32; i += 8) {
        int m = mb + ty + i, k = kb + tx;
        t[ty + i][tx] = (m < M && k < K) ? A[(size_t)m * K + k] : 0.f;
    }
    __syncthreads();
#pragma unroll
    for (int i = 0; i < 32; i += 8) {
        int k = kb + ty + i, m = mb + tx;
        if (m < M) At[(size_t)k * M + m] = t[tx][ty + i];
    }
}

// Wt[y][k][n] = Wsel_y[n][koff_y + k], zero-padded k in [K,128). grid (128,4), block 128
__global__ void prep_wt(const float* __restrict__ Wi, const float* __restrict__ Wo,
                        int ldw, int K, float* __restrict__ Wt) {
    int y = blockIdx.y, k = blockIdx.x, n = threadIdx.x;
    const float* W = (y < 2) ? Wi : Wo;
    int koff = (y & 1) ? K : 0;
    Wt[((y * 128) + k) * 128 + n] = (k < K) ? W[n * ldw + koff + k] : 0.f;
}

// Fused 4-projection GEMM (cp.async double-buffered) + fused att-dot epilogue.
// y=0..3: C_y[M x 128] = A @ Wsel.T using k-major At/Wt. psc pre-zeroed.
__global__ __launch_bounds__(256) void gemm4(
    const float* __restrict__ At, int M, int K,
    const float* __restrict__ Wt,
    const float* __restrict__ ai, const float* __restrict__ ao,
    float* __restrict__ uA, float* __restrict__ vA,
    float* __restrict__ uB, float* __restrict__ vB,
    float* __restrict__ psc)
{
    int y = blockIdx.y;
    const float* att = (y < 2) ? ai : ao;
    float* C = (y == 0) ? uA : (y == 1) ? vA : (y == 2) ? uB : vB;
    const float* Wy = Wt + y * 128 * 128;

    __shared__ float As[2][16][128];
    __shared__ float Bs[2][16][128];

    int m0 = blockIdx.x * 128;
    int tid = threadIdx.x;
    int tx = tid & 15;   // n: tx*8
    int ty = tid >> 4;   // m: ty*8
    float acc[8][8] = {};

    int KT = (K + 15) / 16;   // zero-padding makes extra k's harmless

    // staging helper (macro-style via lambda on constants)
#define STAGE_TILE(T, BUF)                                                         \
    {                                                                              \
        int k0 = (T) * 16;                                                         \
        uint32_t sA = s2u(&As[BUF][0][0]);                                         \
        uint32_t sB = s2u(&Bs[BUF][0][0]);                                         \
        _Pragma("unroll")                                                          \
        for (int i = 0; i < 2; i++) {                                              \
            int ch = tid + i * 256;                                                \
            int row = ch >> 5;                                                     \
            int coff = (ch & 31) * 4;                                              \
            uint32_t ok = (m0 + coff < M) ? 16u : 0u;                              \
            const float* ga = At + (size_t)(k0 + row) * M + (ok ? (m0 + coff) : 0);\
            asm volatile("cp.async.cg.shared.global [%0], [%1], 16, %2;"           \
                         :: "r"(sA + (uint32_t)((row * 128 + coff) * 4)),          \
                            "l"(ga), "r"(ok));                                     \
            const float* gb = Wy + (k0 + row) * 128 + coff;                        \
            asm volatile("cp.async.cg.shared.global [%0], [%1], 16;"               \
                         :: "r"(sB + (uint32_t)((row * 128 + coff) * 4)),          \
                            "l"(gb));                                              \
        }                                                                          \
        asm volatile("cp.async.commit_group;");                                    \
    }

    STAGE_TILE(0, 0);

    for (int t = 0; t < KT; t++) {
        int buf = t & 1;
        if (t + 1 < KT) {
            STAGE_TILE(t + 1, buf ^ 1);
            asm volatile("cp.async.wait_group 1;");
        } else {
            asm volatile("cp.async.wait_group 0;");
        }
        __syncthreads();
        const float(*Ab)[128] = As[buf];
        const float(*Bb)[128] = Bs[buf];
#pragma unroll
        for (int k = 0; k < 16; k++) {
            float4 a0 = *(const float4*)&Ab[k][ty * 8];
            float4 a1 = *(const float4*)&Ab[k][ty * 8 + 4];
            float4 b0 = *(const float4*)&Bb[k][tx * 8];
            float4 b1 = *(const float4*)&Bb[k][tx * 8 + 4];
            float av[8] = {a0.x, a0.y, a0.z, a0.w, a1.x, a1.y, a1.z, a1.w};
            float bv[8] = {b0.x, b0.y, b0.z, b0.w, b1.x, b1.y, b1.z, b1.w};
#pragma unroll
            for (int i = 0; i < 8; i++)
#pragma unroll
                for (int j = 0; j < 8; j++)
                    acc[i][j] = fmaf(av[i], bv[j], acc[i][j]);
        }
        __syncthreads();
    }
#undef STAGE_TILE

    // store C tile
#pragma unroll
    for (int i = 0; i < 8; i++) {
        int gm = m0 + ty * 8 + i;
        if (gm >= M) continue;
#pragma unroll
        for (int j = 0; j < 8; j += 4) {
            float4 v = make_float4(acc[i][j], acc[i][j + 1], acc[i][j + 2], acc[i][j + 3]);
            *(float4*)&C[(size_t)gm * 128 + tx * 8 + j] = v;
        }
    }

    // fused att-dot epilogue: columns tx*8..tx*8+7 lie in head h = tx>>3.
    int h = tx >> 3;
    float attv[8];
#pragma unroll
    for (int j = 0; j < 8; j++) attv[j] = att[tx * 8 + j];
#pragma unroll
    for (int i = 0; i < 8; i++) {
        float pp = 0.f;
#pragma unroll
        for (int j = 0; j < 8; j++) pp = fmaf(attv[j], acc[i][j], pp);
#pragma unroll
        for (int o = 1; o < 8; o <<= 1) pp += __shfl_xor_sync(0xffffffffu, pp, o);
        int gm = m0 + ty * 8 + i;
        if ((tx & 7) == 0 && gm < M)
            atomicAdd(&psc[gm * 8 + y * 2 + h], pp);
    }
}

// C[M x N] = A[M x K] @ W.T (+bias) — entity layer
__global__ __launch_bounds__(256) void gemm_wt(
    const float* __restrict__ A, int lda,
    const float* __restrict__ W, int ldw, int K,
    const float* __restrict__ bias,
    float* __restrict__ C, int ldc, int M)
{
    __shared__ float As[64][17];
    __shared__ float Bs[16][65];
    int m0 = blockIdx.x * 64, n0 = blockIdx.y * 64;
    int tx = threadIdx.x & 15, ty = threadIdx.x >> 4;
    float acc[4][4] = {};
    for (int k0 = 0; k0 < K; k0 += 16) {
#pragma unroll
        for (int i = 0; i < 4; i++) {
            int li = threadIdx.x + i * 256;
            int k = li & 15, m = li >> 4;
            int gm = m0 + m, gk = k0 + k;
            As[m][k] = (gm < M && gk < K) ? A[gm * lda + gk] : 0.f;
        }
#pragma unroll
        for (int i = 0; i < 4; i++) {
            int li = threadIdx.x + i * 256;
            int k = li & 15, n = li >> 4;
            int gk = k0 + k;
            Bs[k][n] = (gk < K) ? W[(n0 + n) * ldw + gk] : 0.f;
        }
        __syncthreads();
#pragma unroll
        for (int k = 0; k < 16; k++) {
            float a[4], b[4];
#pragma unroll
            for (int i = 0; i < 4; i++) a[i] = As[ty * 4 + i][k];
#pragma unroll
            for (int j = 0; j < 4; j++) b[j] = Bs[k][tx * 4 + j];
#pragma unroll
            for (int i = 0; i < 4; i++)
#pragma unroll
                for (int j = 0; j < 4; j++)
                    acc[i][j] = fmaf(a[i], b[j], acc[i][j]);
        }
        __syncthreads();
    }
#pragma unroll
    for (int i = 0; i < 4; i++) {
        int gm = m0 + ty * 4 + i;
        if (gm >= M) continue;
#pragma unroll
        for (int j = 0; j < 4; j++) {
            int gn = n0 + tx * 4 + j;
            C[gm * ldc + gn] = acc[i][j] + bias[gn];
        }
    }
}

// Relation projection for both directions + fused aw reduction (packed output).
__global__ void relproj2(const float* __restrict__ g,
                         const float* __restrict__ Wi, const float* __restrict__ bi,
                         const float* __restrict__ ai,
                         const float* __restrict__ Wo, const float* __restrict__ bo,
                         const float* __restrict__ ao,
                         int ldw, int koff,
                         float* __restrict__ wA, float* __restrict__ wB,
                         float* __restrict__ paw)
{
    int r = blockIdx.x, y = blockIdx.y;
    const float* W = y ? Wo : Wi;
    const float* b = y ? bo : bi;
    const float* att = y ? ao : ai;
    float* wout = y ? wB : wA;
    __shared__ float gs[GS];
    int n = threadIdx.x;
    if (n < GS) gs[n] = g[r * GS + n];
    __syncthreads();
    float acc = b[n];
    const float* wr = W + n * ldw + koff;
#pragma unroll 4
    for (int k = 0; k < GS; k++) acc = fmaf(wr[k], gs[k], acc);
    wout[r * 128 + n] = acc;
    float s = wsum(acc * att[n]);
    __shared__ float sm[4];
    if ((n & 31) == 0) sm[n >> 5] = s;
    __syncthreads();
    if (n == 0) paw[r * 4 + y * 2 + 0] = sm[0] + sm[1];
    if (n == 64) paw[r * 4 + y * 2 + 1] = sm[2] + sm[3];
}

// g_prime: block per relation
__global__ void relproj_out(const float* __restrict__ g, const float* __restrict__ Wr,
                            const float* __restrict__ br, float* __restrict__ out)
{
    int r = blockIdx.x;
    __shared__ float gs[GS];
    int n = threadIdx.x;
    if (n < GS) gs[n] = g[r * GS + n];
    __syncthreads();
    float acc = br[n];
    const float* wr = Wr + n * GS;
#pragma unroll 4
    for (int k = 0; k < GS; k++) acc = fmaf(wr[k], gs[k], acc);
    out[r * 128 + n] = acc;
}

// Fused pass A for both directions: one thread per edge, packed-scalar gathers.
__global__ __launch_bounds__(256) void pass_a2(
    const int* __restrict__ rowp, const int* __restrict__ colp, const int* __restrict__ et,
    const float* __restrict__ psc, const float* __restrict__ paw,
    float* __restrict__ ebA, float* __restrict__ ebB,
    float* __restrict__ denA, float* __restrict__ denB)
{
    int e = blockIdx.x * blockDim.x + threadIdx.x;
    if (e >= EE) return;
    int r = rowp[e], c = colp[e], t = et[e];
    float4 r0 = *(const float4*)&psc[r * 8];
    float4 r1 = *(const float4*)&psc[r * 8 + 4];
    float4 c0 = *(const float4*)&psc[c * 8];
    float4 c1 = *(const float4*)&psc[c * 8 + 4];
    float4 aw = *(const float4*)&paw[t * 4];

    float a0 = r0.x + c0.z + aw.x;
    float a1 = r0.y + c0.w + aw.y;
    float b0 = c1.x + r1.z + aw.z;
    float b1 = c1.y + r1.w + aw.w;

    a0 = (a0 > 0.f) ? a0 : kNEG * a0;
    a1 = (a1 > 0.f) ? a1 : kNEG * a1;
    b0 = (b0 > 0.f) ? b0 : kNEG * b0;
    b1 = (b1 > 0.f) ? b1 : kNEG * b1;
    float ea0 = expf(a0), ea1 = expf(a1), eb0 = expf(b0), eb1 = expf(b1);
    *(float2*)&ebA[e * 2] = make_float2(ea0, ea1);
    *(float2*)&ebB[e * 2] = make_float2(eb0, eb1);
    atomicAdd(&denA[r * 2 + 0], ea0);
    atomicAdd(&denA[r * 2 + 1], ea1);
    atomicAdd(&denB[c * 2 + 0], eb0);
    atomicAdd(&denB[c * 2 + 1], eb1);
}

// Fused pass B for both directions: warp per edge.
__global__ __launch_bounds__(256) void pass_b2(
    const int* __restrict__ rowp, const int* __restrict__ colp, const int* __restrict__ et,
    const float* __restrict__ uA, const float* __restrict__ wA,
    const float* __restrict__ uB, const float* __restrict__ wB,
    const float* __restrict__ ebA, const float* __restrict__ denA,
    const float* __restrict__ ebB, const float* __restrict__ denB,
    float* __restrict__ accA, float* __restrict__ salA,
    float* __restrict__ accB, float* __restrict__ salB)
{
    int e = blockIdx.x * 8 + (threadIdx.x >> 5);
    if (e >= EE) return;
    int l = threadIdx.x & 31;
    int r = rowp[e], c = colp[e], t = et[e];
    int h = l >> 4;
    float aA = ebA[e * 2 + h] / denA[r * 2 + h];
    float aB = ebB[e * 2 + h] / denB[c * 2 + h];

    {
        float4 uv = ((const float4*)(uA + (size_t)r * 128))[l];
        float4 wv = ((const float4*)(wA + (size_t)t * 128))[l];
        float4 o;
        o.x = aA * (uv.x + wv.x); o.y = aA * (uv.y + wv.y);
        o.z = aA * (uv.z + wv.z); o.w = aA * (uv.w + wv.w);
        float* dst = accA + (size_t)c * 128 + l * 4;
        asm volatile("red.global.add.v4.f32 [%0], {%1, %2, %3, %4};"
                     :: "l"(dst), "f"(o.x), "f"(o.y), "f"(o.z), "f"(o.w) : "memory");
    }
    {
        float4 uv = ((const float4*)(uB + (size_t)c * 128))[l];
        float4 wv = ((const float4*)(wB + (size_t)t * 128))[l];
        float4 o;
        o.x = aB * (uv.x + wv.x); o.y = aB * (uv.y + wv.y);
        o.z = aB * (uv.z + wv.z); o.w = aB * (uv.w + wv.w);
        float* dst = accB + (size_t)r * 128 + l * 4;
        asm volatile("red.global.add.v4.f32 [%0], {%1, %2, %3, %4};"
                     :: "l"(dst), "f"(o.x), "f"(o.y), "f"(o.z), "f"(o.w) : "memory");
    }
    if (l == 0)  { atomicAdd(&salA[c * 2 + 0], aA); atomicAdd(&salB[r * 2 + 0], aB); }
    if (l == 16) { atomicAdd(&salA[c * 2 + 1], aA); atomicAdd(&salB[r * 2 + 1], aB); }
}

// out = l2norm_per_head(leaky(0.5*(accA + salA*vA) + 0.5*(accB + salB*vB)))
__global__ void combine(const float* __restrict__ accA, const float* __restrict__ salA,
                        const float* __restrict__ vA,
                        const float* __restrict__ accB, const float* __restrict__ salB,
                        const float* __restrict__ vB,
                        float* __restrict__ out)
{
    int i = blockIdx.x, j = threadIdx.x;
    int h = j >> 6;
    float a = accA[i * 128 + j] + salA[i * 2 + h] * vA[i * 128 + j];
    float b = accB[i * 128 + j] + salB[i * 2 + h] * vB[i * 128 + j];
    float v = 0.5f * (a + b);
    v = (v > 0.f) ? v : kNEG * v;
    float s = wsum(v * v);
    __shared__ float sm[4];
    if ((j & 31) == 0) sm[j >> 5] = s;
    __syncthreads();
    float tot = sm[h * 2] + sm[h * 2 + 1];
    out[i * 128 + j] = v / fmaxf(sqrtf(tot), kEPS);
}

// h_prime = l2norm_128(ent broadcast over heads + h)
__global__ void final_k(const float* __restrict__ ent, const float* __restrict__ h,
                        float* __restrict__ out)
{
    int i = blockIdx.x, j = threadIdx.x;
    float v = ent[i * 64 + (j & 63)] + h[i * 128 + j];
    float s = wsum(v * v);
    __shared__ float sm[4];
    if ((j & 31) == 0) sm[j >> 5] = s;
    __syncthreads();
    float tot = sm[0] + sm[1] + sm[2] + sm[3];
    out[i * 128 + j] = v / fmaxf(sqrtf(tot), kEPS);
}

// ------------------------- host orchestration -------------------------
namespace {
struct Ptrs {
    float *xn, *At, *Wt, *uA, *vA, *uB, *vB, *accA, *accB, *salA, *salB, *h, *ent, *wA, *wB;
    float *psc, *paw, *ebA, *ebB, *denA, *denB;
};

static void get_ptrs(Ptrs& p) {
    cudaGetSymbolAddress((void**)&p.xn, d_xn);
    cudaGetSymbolAddress((void**)&p.At, d_At);
    cudaGetSymbolAddress((void**)&p.Wt, d_Wt);
    cudaGetSymbolAddress((void**)&p.uA, d_uA);
    cudaGetSymbolAddress((void**)&p.vA, d_vA);
    cudaGetSymbolAddress((void**)&p.uB, d_uB);
    cudaGetSymbolAddress((void**)&p.vB, d_vB);
    cudaGetSymbolAddress((void**)&p.accA, d_accA);
    cudaGetSymbolAddress((void**)&p.accB, d_accB);
    cudaGetSymbolAddress((void**)&p.salA, d_salA);
    cudaGetSymbolAddress((void**)&p.salB, d_salB);
    cudaGetSymbolAddress((void**)&p.h, d_h);
    cudaGetSymbolAddress((void**)&p.ent, d_ent);
    cudaGetSymbolAddress((void**)&p.wA, d_wA);
    cudaGetSymbolAddress((void**)&p.wB, d_wB);
    cudaGetSymbolAddress((void**)&p.psc, d_psc);
    cudaGetSymbolAddress((void**)&p.paw, d_paw);
    cudaGetSymbolAddress((void**)&p.ebA, d_ebA);
    cudaGetSymbolAddress((void**)&p.ebB, d_ebB);
    cudaGetSymbolAddress((void**)&p.denA, d_denA);
    cudaGetSymbolAddress((void**)&p.denB, d_denB);
}

static void run_layer(const Ptrs& p,
                      const float* A, int K, int ldw,
                      const float* Wi, const float* bi, const float* ai,
                      const float* Wo, const float* bo, const float* ao,
                      const float* g,
                      const int* rowp, const int* colp, const int* et,
                      float* outH)
{
    // k-major staging for cp.async GEMM
    transpose_A<<<dim3((NN + 31) / 32, 4), dim3(32, 8)>>>(A, NN, K, p.At);
    prep_wt<<<dim3(128, 4), 128>>>(Wi, Wo, ldw, K, p.Wt);
    // zero packed att-scalar accumulator before gemm4's fused epilogue
    cudaMemsetAsync(p.psc, 0, NN * 8 * sizeof(float));
    // node projections (4 fused, cp.async pipelined) + fused att-dot epilogue
    dim3 gg((NN + 127) / 128, 4);
    gemm4<<<gg, 256>>>(p.At, NN, K, p.Wt, ai, ao,
                       p.uA, p.vA, p.uB, p.vB, p.psc);
    // relation projections + packed aw
    dim3 gr(RR, 2);
    relproj2<<<gr, 128>>>(g, Wi, bi, ai, Wo, bo, ao, ldw, 2 * K,
                          p.wA, p.wB, p.paw);
    // zero accumulators
    cudaMemsetAsync(p.accA, 0, NN * 128 * sizeof(float));
    cudaMemsetAsync(p.accB, 0, NN * 128 * sizeof(float));
    cudaMemsetAsync(p.salA, 0, NN * 2 * sizeof(float));
    cudaMemsetAsync(p.salB, 0, NN * 2 * sizeof(float));
    cudaMemsetAsync(p.denA, 0, NN * 2 * sizeof(float));
    cudaMemsetAsync(p.denB, 0, NN * 2 * sizeof(float));
    // edge passes (both directions fused)
    pass_a2<<<(EE + 255) / 256, 256>>>(rowp, colp, et, p.psc, p.paw,
                                       p.ebA, p.ebB, p.denA, p.denB);
    pass_b2<<<(EE + 7) / 8, 256>>>(rowp, colp, et, p.uA, p.wA, p.uB, p.wB,
                                   p.ebA, p.denA, p.ebB, p.denB,
                                   p.accA, p.salA, p.accB, p.salB);
    combine<<<NN, 128>>>(p.accA, p.salA, p.vA, p.accB, p.salB, p.vB, outH);
}
}  // namespace

extern "C" void kernel_launch(void* const* d_in, const int* in_sizes, int n_in,
                              void* d_out, int out_size)
{
    const float* x   = (const float*)d_in[0];
    const float* g   = (const float*)d_in[1];
    const int*   ei  = (const int*)d_in[2];
    const int*   et  = (const int*)d_in[3];
    const float* W1i = (const float*)d_in[4];
    const float* b1i = (const float*)d_in[5];
    const float* a1i = (const float*)d_in[6];
    const float* W1o = (const float*)d_in[7];
    const float* b1o = (const float*)d_in[8];
    const float* a1o = (const float*)d_in[9];
    const float* W2i = (const float*)d_in[10];
    const float* b2i = (const float*)d_in[11];
    const float* a2i = (const float*)d_in[12];
    const float* W2o = (const float*)d_in[13];
    const float* b2o = (const float*)d_in[14];
    const float* a2o = (const float*)d_in[15];
    const float* We  = (const float*)d_in[16];
    const float* be  = (const float*)d_in[17];
    const float* Wr  = (const float*)d_in[18];
    const float* br  = (const float*)d_in[19];
    float* out = (float*)d_out;

    const int* rowp = ei;
    const int* colp = ei + EE;

    Ptrs p;
    get_ptrs(p);

    norm_x<<<NN, 128>>>(x, p.xn);

    // layer 1: input xn [NN,100], d1 = 300
    run_layer(p, p.xn, XS, 2 * XS + GS,
              W1i, b1i, a1i, W1o, b1o, a1o, g, rowp, colp, et, p.h);

    // layer 2: input h [NN,128], d2 = 356
    run_layer(p, p.h, 128, 2 * 128 + GS,
              W2i, b2i, a2i, W2o, b2o, a2o, g, rowp, colp, et, p.h);

    // entity layer: ent = xn @ We.T + be  [NN,64]
    dim3 ge((NN + 63) / 64, 1);
    gemm_wt<<<ge, 256>>>(p.xn, XS, We, XS, XS, be, p.ent, 64, NN);

    // h_prime -> out[0 : NN*128)
    final_k<<<NN, 128>>>(p.ent, p.h, out);

    // g_prime -> out[NN*128 : NN*128 + RR*128)
    relproj_out<<<RR, 128>>>(g, Wr, br, out + NN * 128);
}

// round 8
// speedup vs baseline: 1.2406x; 1.0124x over previous
#include <cuda_runtime.h>
#include <math.h>
#include <stdint.h>

#define NN 50000
#define EE 400000
#define RR 500
#define XS 100
#define GS 100

static __device__ __constant__ float kNEG = 0.01f;
static __device__ __constant__ float kEPS = 1e-12f;

// ------------------------- scratch (device globals) -------------------------
__device__ float d_xn[NN * XS];
__device__ float d_At[128 * NN];        // k-major transposed activations (zero-padded)
__device__ float d_Wt[4 * 128 * 128];   // k-major weight slices per projection y
__device__ float d_uA[NN * 128];
__device__ float d_vA[NN * 128];
__device__ float d_uB[NN * 128];
__device__ float d_vB[NN * 128];
__device__ float d_accA[NN * 128];
__device__ float d_accB[NN * 128];
__device__ float d_salA[NN * 2];
__device__ float d_salB[NN * 2];
__device__ float d_h[NN * 128];
__device__ float d_ent[NN * 64];
__device__ float d_wA[RR * 128];
__device__ float d_wB[RR * 128];
__device__ float d_psc[NN * 8];
__device__ float d_paw[RR * 4];
__device__ float d_ebA[EE * 2];
__device__ float d_ebB[EE * 2];
__device__ float d_denA[NN * 2];
__device__ float d_denB[NN * 2];
// edge sort scratch: [0,NN) = counts by col (dirA dest), [NN,2NN) by row (dirB dest)
__device__ int d_counts[2 * NN];
__device__ int d_cur[2 * NN];
__device__ int d_offs[2 * NN];
__device__ int d_csum[256];
__device__ int d_perm[2 * EE];  // [0,EE): edges sorted by col; [EE,2EE): by row

// ------------------------- helpers -------------------------
__device__ __forceinline__ float wsum(float v) {
#pragma unroll
    for (int o = 16; o > 0; o >>= 1) v += __shfl_xor_sync(0xffffffffu, v, o);
    return v;
}

__device__ __forceinline__ uint32_t s2u(const void* p) {
    return (uint32_t)__cvta_generic_to_shared(p);
}

// L2-normalize rows of x [NN, XS]
__global__ void norm_x(const float* __restrict__ x, float* __restrict__ xn) {
    int i = blockIdx.x;
    int j = threadIdx.x;
    float v = (j < XS) ? x[i * XS + j] : 0.f;
    float s = wsum(v * v);
    __shared__ float sm[4];
    if ((j & 31) == 0) sm[j >> 5] = s;
    __syncthreads();
    float tot = sm[0] + sm[1] + sm[2] + sm[3];
    if (j < XS) xn[i * XS + j] = v / fmaxf(sqrtf(tot), kEPS);
}

// ------------------------- edge counting sort -------------------------
__global__ void hist_k(const int* __restrict__ rowp, const int* __restrict__ colp,
                       int* __restrict__ counts) {
    int e = blockIdx.x * blockDim.x + threadIdx.x;
    if (e >= EE) return;
    atomicAdd(&counts[colp[e]], 1);
    atomicAdd(&counts[NN + rowp[e]], 1);
}

__global__ void scan1(const int* __restrict__ counts, int* __restrict__ offs,
                      int* __restrict__ csum, int M) {
    __shared__ int sm[512];
    int i = threadIdx.x, g = blockIdx.x * 512 + i;
    int v = (g < M) ? counts[g] : 0;
    sm[i] = v;
    __syncthreads();
    for (int o = 1; o < 512; o <<= 1) {
        int t = (i >= o) ? sm[i - o] : 0;
        __syncthreads();
        sm[i] += t;
        __syncthreads();
    }
    if (g < M) offs[g] = sm[i] - v;
    if (i == 511) csum[blockIdx.x] = sm[511];
}

__global__ void scan2(int* __restrict__ csum, int NB) {
    __shared__ int sm[256];
    int i = threadIdx.x;
    int v = (i < NB) ? csum[i] : 0;
    sm[i] = v;
    __syncthreads();
    for (int o = 1; o < 256; o <<= 1) {
        int t = (i >= o) ? sm[i - o] : 0;
        __syncthreads();
        sm[i] += t;
        __syncthreads();
    }
    if (i < NB) csum[i] = sm[i] - v;
}

__global__ void scan3(int* __restrict__ offs, const int* __restrict__ csum, int M) {
    int g = blockIdx.x * 256 + threadIdx.x;
    if (g < M) offs[g] += csum[g >> 9];
}

__global__ void scatter_k(const int* __restrict__ rowp, const int* __restrict__ colp,
                          const int* __restrict__ offs, int* __restrict__ cur,
                          int* __restrict__ perm) {
    int e = blockIdx.x * blockDim.x + threadIdx.x;
    if (e >= EE) return;
    int c = colp[e];
    perm[offs[c] + atomicAdd(&cur[c], 1)] = e;
    int r = rowp[e];
    perm[offs[NN + r] + atomicAdd(&cur[NN + r], 1)] = e;
}

// At[k][m] = A[m][k], zero-padded rows k in [K, 128)
__global__ void transpose_A(const float* __restrict__ A, int M, int K,
                            float* __restrict__ At) {
    __shared__ float t[32][33];
    int mb = blockIdx.x * 32, kb = blockIdx.y * 32;
    int tx = threadIdx.x, ty = threadIdx.y;
#pragma unroll
    for (int i = 0; i < 32; i += 8) {
        int m = mb + ty + i, k = kb + tx;
        t[ty + i][tx] = (m < M && k < K) ? A[(size_t)m * K + k] : 0.f;
    }
    __syncthreads();
#pragma unroll
    for (int i = 0; i < 32; i += 8) {
        int k = kb + ty + i, m = mb + tx;
        if (m < M) At[(size_t)k * M + m] = t[tx][ty + i];
    }
}

// Wt[y][k][n] = Wsel_y[n][koff_y + k], zero-padded
__global__ void prep_wt(const float* __restrict__ Wi, const float* __restrict__ Wo,
                        int ldw, int K, float* __restrict__ Wt) {
    int y = blockIdx.y, k = blockIdx.x, n = threadIdx.x;
    const float* W = (y < 2) ? Wi : Wo;
    int koff = (y & 1) ? K : 0;
    Wt[((y * 128) + k) * 128 + n] = (k < K) ? W[n * ldw + koff + k] : 0.f;
}

// Fused 4-projection GEMM (cp.async double-buffered) + fused att-dot epilogue.
__global__ __launch_bounds__(256) void gemm4(
    const float* __restrict__ At, int M, int K,
    const float* __restrict__ Wt,
    const float* __restrict__ ai, const float* __restrict__ ao,
    float* __restrict__ uA, float* __restrict__ vA,
    float* __restrict__ uB, float* __restrict__ vB,
    float* __restrict__ psc)
{
    int y = blockIdx.y;
    const float* att = (y < 2) ? ai : ao;
    float* C = (y == 0) ? uA : (y == 1) ? vA : (y == 2) ? uB : vB;
    const float* Wy = Wt + y * 128 * 128;

    __shared__ float As[2][16][128];
    __shared__ float Bs[2][16][128];

    int m0 = blockIdx.x * 128;
    int tid = threadIdx.x;
    int tx = tid & 15;
    int ty = tid >> 4;
    float acc[8][8] = {};

    int KT = (K + 15) / 16;

#define STAGE_TILE(T, BUF)                                                         \
    {                                                                              \
        int k0 = (T) * 16;                                                         \
        uint32_t sA = s2u(&As[BUF][0][0]);                                         \
        uint32_t sB = s2u(&Bs[BUF][0][0]);                                         \
        _Pragma("unroll")                                                          \
        for (int i = 0; i < 2; i++) {                                              \
            int ch = tid + i * 256;                                                \
            int row = ch >> 5;                                                     \
            int coff = (ch & 31) * 4;                                              \
            uint32_t ok = (m0 + coff < M) ? 16u : 0u;                              \
            const float* ga = At + (size_t)(k0 + row) * M + (ok ? (m0 + coff) : 0);\
            asm volatile("cp.async.cg.shared.global [%0], [%1], 16, %2;"           \
                         :: "r"(sA + (uint32_t)((row * 128 + coff) * 4)),          \
                            "l"(ga), "r"(ok));                                     \
            const float* gb = Wy + (k0 + row) * 128 + coff;                        \
            asm volatile("cp.async.cg.shared.global [%0], [%1], 16;"               \
                         :: "r"(sB + (uint32_t)((row * 128 + coff) * 4)),          \
                            "l"(gb));                                              \
        }                                                                          \
        asm volatile("cp.async.commit_group;");                                    \
    }

    STAGE_TILE(0, 0);

    for (int t = 0; t < KT; t++) {
        int buf = t & 1;
        if (t + 1 < KT) {
            STAGE_TILE(t + 1, buf ^ 1);
            asm volatile("cp.async.wait_group 1;");
        } else {
            asm volatile("cp.async.wait_group 0;");
        }
        __syncthreads();
        const float(*Ab)[128] = As[buf];
        const float(*Bb)[128] = Bs[buf];
#pragma unroll
        for (int k = 0; k < 16; k++) {
            float4 a0 = *(const float4*)&Ab[k][ty * 8];
            float4 a1 = *(const float4*)&Ab[k][ty * 8 + 4];
            float4 b0 = *(const float4*)&Bb[k][tx * 8];
            float4 b1 = *(const float4*)&Bb[k][tx * 8 + 4];
            float av[8] = {a0.x, a0.y, a0.z, a0.w, a1.x, a1.y, a1.z, a1.w};
            float bv[8] = {b0.x, b0.y, b0.z, b0.w, b1.x, b1.y, b1.z, b1.w};
#pragma unroll
            for (int i = 0; i < 8; i++)
#pragma unroll
                for (int j = 0; j < 8; j++)
                    acc[i][j] = fmaf(av[i], bv[j], acc[i][j]);
        }
        __syncthreads();
    }
#undef STAGE_TILE

#pragma unroll
    for (int i = 0; i < 8; i++) {
        int gm = m0 + ty * 8 + i;
        if (gm >= M) continue;
#pragma unroll
        for (int j = 0; j < 8; j += 4) {
            float4 v = make_float4(acc[i][j], acc[i][j + 1], acc[i][j + 2], acc[i][j + 3]);
            *(float4*)&C[(size_t)gm * 128 + tx * 8 + j] = v;
        }
    }

    int h = tx >> 3;
    float attv[8];
#pragma unroll
    for (int j = 0; j < 8; j++) attv[j] = att[tx * 8 + j];
#pragma unroll
    for (int i = 0; i < 8; i++) {
        float pp = 0.f;
#pragma unroll
        for (int j = 0; j < 8; j++) pp = fmaf(attv[j], acc[i][j], pp);
#pragma unroll
        for (int o = 1; o < 8; o <<= 1) pp += __shfl_xor_sync(0xffffffffu, pp, o);
        int gm = m0 + ty * 8 + i;
        if ((tx & 7) == 0 && gm < M)
            atomicAdd(&psc[gm * 8 + y * 2 + h], pp);
    }
}

// C[M x N] = A[M x K] @ W.T (+bias) — entity layer
__global__ __launch_bounds__(256) void gemm_wt(
    const float* __restrict__ A, int lda,
    const float* __restrict__ W, int ldw, int K,
    const float* __restrict__ bias,
    float* __restrict__ C, int ldc, int M)
{
    __shared__ float As[64][17];
    __shared__ float Bs[16][65];
    int m0 = blockIdx.x * 64, n0 = blockIdx.y * 64;
    int tx = threadIdx.x & 15, ty = threadIdx.x >> 4;
    float acc[4][4] = {};
    for (int k0 = 0; k0 < K; k0 += 16) {
#pragma unroll
        for (int i = 0; i < 4; i++) {
            int li = threadIdx.x + i * 256;
            int k = li & 15, m = li >> 4;
            int gm = m0 + m, gk = k0 + k;
            As[m][k] = (gm < M && gk < K) ? A[gm * lda + gk] : 0.f;
        }
#pragma unroll
        for (int i = 0; i < 4; i++) {
            int li = threadIdx.x + i * 256;
            int k = li & 15, n = li >> 4;
            int gk = k0 + k;
            Bs[k][n] = (gk < K) ? W[(n0 + n) * ldw + gk] : 0.f;
        }
        __syncthreads();
#pragma unroll
        for (int k = 0; k < 16; k++) {
            float a[4], b[4];
#pragma unroll
            for (int i = 0; i < 4; i++) a[i] = As[ty * 4 + i][k];
#pragma unroll
            for (int j = 0; j < 4; j++) b[j] = Bs[k][tx * 4 + j];
#pragma unroll
            for (int i = 0; i < 4; i++)
#pragma unroll
                for (int j = 0; j < 4; j++)
                    acc[i][j] = fmaf(a[i], b[j], acc[i][j]);
        }
        __syncthreads();
    }
#pragma unroll
    for (int i = 0; i < 4; i++) {
        int gm = m0 + ty * 4 + i;
        if (gm >= M) continue;
#pragma unroll
        for (int j = 0; j < 4; j++) {
            int gn = n0 + tx * 4 + j;
            C[gm * ldc + gn] = acc[i][j] + bias[gn];
        }
    }
}

// Relation projection for both directions + fused aw reduction (packed output).
__global__ void relproj2(const float* __restrict__ g,
                         const float* __restrict__ Wi, const float* __restrict__ bi,
                         const float* __restrict__ ai,
                         const float* __restrict__ Wo, const float* __restrict__ bo,
                         const float* __restrict__ ao,
                         int ldw, int koff,
                         float* __restrict__ wA, float* __restrict__ wB,
                         float* __restrict__ paw)
{
    int r = blockIdx.x, y = blockIdx.y;
    const float* W = y ? Wo : Wi;
    const float* b = y ? bo : bi;
    const float* att = y ? ao : ai;
    float* wout = y ? wB : wA;
    __shared__ float gs[GS];
    int n = threadIdx.x;
    if (n < GS) gs[n] = g[r * GS + n];
    __syncthreads();
    float acc = b[n];
    const float* wr = W + n * ldw + koff;
#pragma unroll 4
    for (int k = 0; k < GS; k++) acc = fmaf(wr[k], gs[k], acc);
    wout[r * 128 + n] = acc;
    float s = wsum(acc * att[n]);
    __shared__ float sm[4];
    if ((n & 31) == 0) sm[n >> 5] = s;
    __syncthreads();
    if (n == 0) paw[r * 4 + y * 2 + 0] = sm[0] + sm[1];
    if (n == 64) paw[r * 4 + y * 2 + 1] = sm[2] + sm[3];
}

// g_prime: block per relation
__global__ void relproj_out(const float* __restrict__ g, const float* __restrict__ Wr,
                            const float* __restrict__ br, float* __restrict__ out)
{
    int r = blockIdx.x;
    __shared__ float gs[GS];
    int n = threadIdx.x;
    if (n < GS) gs[n] = g[r * GS + n];
    __syncthreads();
    float acc = br[n];
    const float* wr = Wr + n * GS;
#pragma unroll 4
    for (int k = 0; k < GS; k++) acc = fmaf(wr[k], gs[k], acc);
    out[r * 128 + n] = acc;
}

// Fused pass A for both directions: one thread per edge, packed-scalar gathers.
__global__ __launch_bounds__(256) void pass_a2(
    const int* __restrict__ rowp, const int* __restrict__ colp, const int* __restrict__ et,
    const float* __restrict__ psc, const float* __restrict__ paw,
    float* __restrict__ ebA, float* __restrict__ ebB,
    float* __restrict__ denA, float* __restrict__ denB)
{
    int e = blockIdx.x * blockDim.x + threadIdx.x;
    if (e >= EE) return;
    int r = rowp[e], c = colp[e], t = et[e];
    float4 r0 = *(const float4*)&psc[r * 8];
    float4 r1 = *(const float4*)&psc[r * 8 + 4];
    float4 c0 = *(const float4*)&psc[c * 8];
    float4 c1 = *(const float4*)&psc[c * 8 + 4];
    float4 aw = *(const float4*)&paw[t * 4];

    float a0 = r0.x + c0.z + aw.x;
    float a1 = r0.y + c0.w + aw.y;
    float b0 = c1.x + r1.z + aw.z;
    float b1 = c1.y + r1.w + aw.w;

    a0 = (a0 > 0.f) ? a0 : kNEG * a0;
    a1 = (a1 > 0.f) ? a1 : kNEG * a1;
    b0 = (b0 > 0.f) ? b0 : kNEG * b0;
    b1 = (b1 > 0.f) ? b1 : kNEG * b1;
    float ea0 = expf(a0), ea1 = expf(a1), eb0 = expf(b0), eb1 = expf(b1);
    *(float2*)&ebA[e * 2] = make_float2(ea0, ea1);
    *(float2*)&ebB[e * 2] = make_float2(eb0, eb1);
    atomicAdd(&denA[r * 2 + 0], ea0);
    atomicAdd(&denA[r * 2 + 1], ea1);
    atomicAdd(&denB[c * 2 + 0], eb0);
    atomicAdd(&denB[c * 2 + 1], eb1);
}

// Pass B over dest-sorted edges, run-aggregated scatter. grid (ceil(EE/128), 2)
// y=0: dirA (perm[0:EE) sorted by col; src=row, dst=col)
// y=1: dirB (perm[EE:2EE) sorted by row; src=col, dst=row)
__global__ __launch_bounds__(256) void pass_b_sorted(
    const int* __restrict__ perm,
    const int* __restrict__ rowp, const int* __restrict__ colp, const int* __restrict__ et,
    const float* __restrict__ uA, const float* __restrict__ wA,
    const float* __restrict__ ebA, const float* __restrict__ denA,
    float* __restrict__ accA, float* __restrict__ salA,
    const float* __restrict__ uB, const float* __restrict__ wB,
    const float* __restrict__ ebB, const float* __restrict__ denB,
    float* __restrict__ accB, float* __restrict__ salB)
{
    int y = blockIdx.y;
    const int* pm = perm + (y ? EE : 0);
    const int* srcI = y ? colp : rowp;
    const int* dstI = y ? rowp : colp;
    const float* u = y ? uB : uA;
    const float* w = y ? wB : wA;
    const float* eb = y ? ebB : ebA;
    const float* den = y ? denB : denA;
    float* acc = y ? accB : accA;
    float* sal = y ? salB : salA;

    int warp = blockIdx.x * 8 + (threadIdx.x >> 5);
    int l = threadIdx.x & 31;
    int h = l >> 4;
    int p0 = warp * 16;
    if (p0 >= EE) return;
    int pend = (p0 + 16 < EE) ? p0 + 16 : EE;

    int cur = -1;
    float4 a4 = make_float4(0.f, 0.f, 0.f, 0.f);
    float sa = 0.f;

    for (int p = p0; p < pend; p++) {
        int e = pm[p];
        int s = srcI[e], d = dstI[e], t = et[e];
        float alpha = eb[e * 2 + h] / den[s * 2 + h];
        float4 uv = ((const float4*)(u + (size_t)s * 128))[l];
        float4 wv = ((const float4*)(w + (size_t)t * 128))[l];
        if (d != cur) {
            if (cur >= 0) {
                float* dp = acc + (size_t)cur * 128 + l * 4;
                asm volatile("red.global.add.v4.f32 [%0], {%1, %2, %3, %4};"
                             :: "l"(dp), "f"(a4.x), "f"(a4.y), "f"(a4.z), "f"(a4.w)
                             : "memory");
                if (l == 0) atomicAdd(&sal[cur * 2 + 0], sa);
                if (l == 16) atomicAdd(&sal[cur * 2 + 1], sa);
            }
            cur = d;
            a4 = make_float4(0.f, 0.f, 0.f, 0.f);
            sa = 0.f;
        }
        a4.x = fmaf(alpha, uv.x + wv.x, a4.x);
        a4.y = fmaf(alpha, uv.y + wv.y, a4.y);
        a4.z = fmaf(alpha, uv.z + wv.z, a4.z);
        a4.w = fmaf(alpha, uv.w + wv.w, a4.w);
        sa += alpha;
    }
    if (cur >= 0) {
        float* dp = acc + (size_t)cur * 128 + l * 4;
        asm volatile("red.global.add.v4.f32 [%0], {%1, %2, %3, %4};"
                     :: "l"(dp), "f"(a4.x), "f"(a4.y), "f"(a4.z), "f"(a4.w)
                     : "memory");
        if (l == 0) atomicAdd(&sal[cur * 2 + 0], sa);
        if (l == 16) atomicAdd(&sal[cur * 2 + 1], sa);
    }
}

// out = l2norm_per_head(leaky(0.5*(accA + salA*vA) + 0.5*(accB + salB*vB)))
__global__ void combine(const float* __restrict__ accA, const float* __restrict__ salA,
                        const float* __restrict__ vA,
                        const float* __restrict__ accB, const float* __restrict__ salB,
                        const float* __restrict__ vB,
                        float* __restrict__ out)
{
    int i = blockIdx.x, j = threadIdx.x;
    int h = j >> 6;
    float a = accA[i * 128 + j] + salA[i * 2 + h] * vA[i * 128 + j];
    float b = accB[i * 128 + j] + salB[i * 2 + h] * vB[i * 128 + j];
    float v = 0.5f * (a + b);
    v = (v > 0.f) ? v : kNEG * v;
    float s = wsum(v * v);
    __shared__ float sm[4];
    if ((j & 31) == 0) sm[j >> 5] = s;
    __syncthreads();
    float tot = sm[h * 2] + sm[h * 2 + 1];
    out[i * 128 + j] = v / fmaxf(sqrtf(tot), kEPS);
}

// h_prime = l2norm_128(ent broadcast over heads + h)
__global__ void final_k(const float* __restrict__ ent, const float* __restrict__ h,
                        float* __restrict__ out)
{
    int i = blockIdx.x, j = threadIdx.x;
    float v = ent[i * 64 + (j & 63)] + h[i * 128 + j];
    float s = wsum(v * v);
    __shared__ float sm[4];
    if ((j & 31) == 0) sm[j >> 5] = s;
    __syncthreads();
    float tot = sm[0] + sm[1] + sm[2] + sm[3];
    out[i * 128 + j] = v / fmaxf(sqrtf(tot), kEPS);
}

// ------------------------- host orchestration -------------------------
namespace {
struct Ptrs {
    float *xn, *At, *Wt, *uA, *vA, *uB, *vB, *accA, *accB, *salA, *salB, *h, *ent, *wA, *wB;
    float *psc, *paw, *ebA, *ebB, *denA, *denB;
    int *counts, *cur, *offs, *csum, *perm;
};

static void get_ptrs(Ptrs& p) {
    cudaGetSymbolAddress((void**)&p.xn, d_xn);
    cudaGetSymbolAddress((void**)&p.At, d_At);
    cudaGetSymbolAddress((void**)&p.Wt, d_Wt);
    cudaGetSymbolAddress((void**)&p.uA, d_uA);
    cudaGetSymbolAddress((void**)&p.vA, d_vA);
    cudaGetSymbolAddress((void**)&p.uB, d_uB);
    cudaGetSymbolAddress((void**)&p.vB, d_vB);
    cudaGetSymbolAddress((void**)&p.accA, d_accA);
    cudaGetSymbolAddress((void**)&p.accB, d_accB);
    cudaGetSymbolAddress((void**)&p.salA, d_salA);
    cudaGetSymbolAddress((void**)&p.salB, d_salB);
    cudaGetSymbolAddress((void**)&p.h, d_h);
    cudaGetSymbolAddress((void**)&p.ent, d_ent);
    cudaGetSymbolAddress((void**)&p.wA, d_wA);
    cudaGetSymbolAddress((void**)&p.wB, d_wB);
    cudaGetSymbolAddress((void**)&p.psc, d_psc);
    cudaGetSymbolAddress((void**)&p.paw, d_paw);
    cudaGetSymbolAddress((void**)&p.ebA, d_ebA);
    cudaGetSymbolAddress((void**)&p.ebB, d_ebB);
    cudaGetSymbolAddress((void**)&p.denA, d_denA);
    cudaGetSymbolAddress((void**)&p.denB, d_denB);
    cudaGetSymbolAddress((void**)&p.counts, d_counts);
    cudaGetSymbolAddress((void**)&p.cur, d_cur);
    cudaGetSymbolAddress((void**)&p.offs, d_offs);
    cudaGetSymbolAddress((void**)&p.csum, d_csum);
    cudaGetSymbolAddress((void**)&p.perm, d_perm);
}

static void run_layer(const Ptrs& p,
                      const float* A, int K, int ldw,
                      const float* Wi, const float* bi, const float* ai,
                      const float* Wo, const float* bo, const float* ao,
                      const float* g,
                      const int* rowp, const int* colp, const int* et,
                      float* outH)
{
    transpose_A<<<dim3((NN + 31) / 32, 4), dim3(32, 8)>>>(A, NN, K, p.At);
    prep_wt<<<dim3(128, 4), 128>>>(Wi, Wo, ldw, K, p.Wt);
    cudaMemsetAsync(p.psc, 0, NN * 8 * sizeof(float));
    dim3 gg((NN + 127) / 128, 4);
    gemm4<<<gg, 256>>>(p.At, NN, K, p.Wt, ai, ao,
                       p.uA, p.vA, p.uB, p.vB, p.psc);
    dim3 gr(RR, 2);
    relproj2<<<gr, 128>>>(g, Wi, bi, ai, Wo, bo, ao, ldw, 2 * K,
                          p.wA, p.wB, p.paw);
    cudaMemsetAsync(p.accA, 0, NN * 128 * sizeof(float));
    cudaMemsetAsync(p.accB, 0, NN * 128 * sizeof(float));
    cudaMemsetAsync(p.salA, 0, NN * 2 * sizeof(float));
    cudaMemsetAsync(p.salB, 0, NN * 2 * sizeof(float));
    cudaMemsetAsync(p.denA, 0, NN * 2 * sizeof(float));
    cudaMemsetAsync(p.denB, 0, NN * 2 * sizeof(float));
    pass_a2<<<(EE + 255) / 256, 256>>>(rowp, colp, et, p.psc, p.paw,
                                       p.ebA, p.ebB, p.denA, p.denB);
    dim3 gb((EE + 127) / 128, 2);
    pass_b_sorted<<<gb, 256>>>(p.perm, rowp, colp, et,
                               p.uA, p.wA, p.ebA, p.denA, p.accA, p.salA,
                               p.uB, p.wB, p.ebB, p.denB, p.accB, p.salB);
    combine<<<NN, 128>>>(p.accA, p.salA, p.vA, p.accB, p.salB, p.vB, outH);
}
}  // namespace

extern "C" void kernel_launch(void* const* d_in, const int* in_sizes, int n_in,
                              void* d_out, int out_size)
{
    const float* x   = (const float*)d_in[0];
    const float* g   = (const float*)d_in[1];
    const int*   ei  = (const int*)d_in[2];
    const int*   et  = (const int*)d_in[3];
    const float* W1i = (const float*)d_in[4];
    const float* b1i = (const float*)d_in[5];
    const float* a1i = (const float*)d_in[6];
    const float* W1o = (const float*)d_in[7];
    const float* b1o = (const float*)d_in[8];
    const float* a1o = (const float*)d_in[9];
    const float* W2i = (const float*)d_in[10];
    const float* b2i = (const float*)d_in[11];
    const float* a2i = (const float*)d_in[12];
    const float* W2o = (const float*)d_in[13];
    const float* b2o = (const float*)d_in[14];
    const float* a2o = (const float*)d_in[15];
    const float* We  = (const float*)d_in[16];
    const float* be  = (const float*)d_in[17];
    const float* Wr  = (const float*)d_in[18];
    const float* br  = (const float*)d_in[19];
    float* out = (float*)d_out;

    const int* rowp = ei;
    const int* colp = ei + EE;

    Ptrs p;
    get_ptrs(p);

    // edge counting sort (once per call; shared by both layers & directions)
    const int M2 = 2 * NN;                      // 100000
    const int NB = (M2 + 511) / 512;            // 196
    cudaMemsetAsync(p.counts, 0, M2 * sizeof(int));
    cudaMemsetAsync(p.cur, 0, M2 * sizeof(int));
    hist_k<<<(EE + 255) / 256, 256>>>(rowp, colp, p.counts);
    scan1<<<NB, 512>>>(p.counts, p.offs, p.csum, M2);
    scan2<<<1, 256>>>(p.csum, NB);
    scan3<<<(M2 + 255) / 256, 256>>>(p.offs, p.csum, M2);
    scatter_k<<<(EE + 255) / 256, 256>>>(rowp, colp, p.offs, p.cur, p.perm);

    norm_x<<<NN, 128>>>(x, p.xn);

    // layer 1: input xn [NN,100]
    run_layer(p, p.xn, XS, 2 * XS + GS,
              W1i, b1i, a1i, W1o, b1o, a1o, g, rowp, colp, et, p.h);

    // layer 2: input h [NN,128]
    run_layer(p, p.h, 128, 2 * 128 + GS,
              W2i, b2i, a2i, W2o, b2o, a2o, g, rowp, colp, et, p.h);

    // entity layer
    dim3 ge((NN + 63) / 64, 1);
    gemm_wt<<<ge, 256>>>(p.xn, XS, We, XS, XS, be, p.ent, 64, NN);

    final_k<<<NN, 128>>>(p.ent, p.h, out);
    relproj_out<<<RR, 128>>>(g, Wr, br, out + NN * 128);
}

// round 10
// speedup vs baseline: 1.2464x; 1.0047x over previous
#include <cuda_runtime.h>
#include <math.h>
#include <stdint.h>

#define NN 50000
#define EE 400000
#define RR 500
#define XS 100
#define GS 100

static __device__ __constant__ float kNEG = 0.01f;
static __device__ __constant__ float kEPS = 1e-12f;

// ------------------------- scratch (device globals) -------------------------
__device__ float d_xn[NN * XS];
__device__ float d_At[128 * NN];        // k-major transposed activations (zero-padded)
__device__ float d_Wt[4 * 128 * 128];   // k-major weight slices per projection y
__device__ float d_uA[NN * 128];
__device__ float d_vA[NN * 128];
__device__ float d_uB[NN * 128];
__device__ float d_vB[NN * 128];
__device__ float d_accA[NN * 128];
__device__ float d_accB[NN * 128];
__device__ float d_salA[NN * 2];
__device__ float d_salB[NN * 2];
__device__ float d_h[NN * 128];
__device__ float d_ent[NN * 64];
__device__ float d_wA[RR * 128];
__device__ float d_wB[RR * 128];
__device__ float d_psc[NN * 8];
__device__ float d_paw[RR * 4];
__device__ float d_ebA[EE * 2];
__device__ float d_ebB[EE * 2];
__device__ float d_denA[NN * 2];
__device__ float d_denB[NN * 2];
// edge sort scratch: [0,NN) = counts by col (dirA dest), [NN,2NN) by row (dirB dest)
__device__ int d_counts[2 * NN];
__device__ int d_cur[2 * NN];
__device__ int d_offs[2 * NN];
__device__ int d_csum[256];
__device__ int4 d_edge4[2 * EE];  // sorted edge payload: {src, type, e, 0}

// ------------------------- helpers -------------------------
__device__ __forceinline__ float wsum(float v) {
#pragma unroll
    for (int o = 16; o > 0; o >>= 1) v += __shfl_xor_sync(0xffffffffu, v, o);
    return v;
}

__device__ __forceinline__ uint32_t s2u(const void* p) {
    return (uint32_t)__cvta_generic_to_shared(p);
}

// L2-normalize rows of x [NN, XS]
__global__ void norm_x(const float* __restrict__ x, float* __restrict__ xn) {
    int i = blockIdx.x;
    int j = threadIdx.x;
    float v = (j < XS) ? x[i * XS + j] : 0.f;
    float s = wsum(v * v);
    __shared__ float sm[4];
    if ((j & 31) == 0) sm[j >> 5] = s;
    __syncthreads();
    float tot = sm[0] + sm[1] + sm[2] + sm[3];
    if (j < XS) xn[i * XS + j] = v / fmaxf(sqrtf(tot), kEPS);
}

// ------------------------- edge counting sort -------------------------
__global__ void hist_k(const int* __restrict__ rowp, const int* __restrict__ colp,
                       int* __restrict__ counts) {
    int e = blockIdx.x * blockDim.x + threadIdx.x;
    if (e >= EE) return;
    atomicAdd(&counts[colp[e]], 1);
    atomicAdd(&counts[NN + rowp[e]], 1);
}

__global__ void scan1(const int* __restrict__ counts, int* __restrict__ offs,
                      int* __restrict__ csum, int M) {
    __shared__ int sm[512];
    int i = threadIdx.x, g = blockIdx.x * 512 + i;
    int v = (g < M) ? counts[g] : 0;
    sm[i] = v;
    __syncthreads();
    for (int o = 1; o < 512; o <<= 1) {
        int t = (i >= o) ? sm[i - o] : 0;
        __syncthreads();
        sm[i] += t;
        __syncthreads();
    }
    if (g < M) offs[g] = sm[i] - v;
    if (i == 511) csum[blockIdx.x] = sm[511];
}

__global__ void scan2(int* __restrict__ csum, int NB) {
    __shared__ int sm[256];
    int i = threadIdx.x;
    int v = (i < NB) ? csum[i] : 0;
    sm[i] = v;
    __syncthreads();
    for (int o = 1; o < 256; o <<= 1) {
        int t = (i >= o) ? sm[i - o] : 0;
        __syncthreads();
        sm[i] += t;
        __syncthreads();
    }
    if (i < NB) csum[i] = sm[i] - v;
}

__global__ void scan3(int* __restrict__ offs, const int* __restrict__ csum, int M) {
    int g = blockIdx.x * 256 + threadIdx.x;
    if (g < M) offs[g] += csum[g >> 9];
}

__global__ void scatter_k(const int* __restrict__ rowp, const int* __restrict__ colp,
                          const int* __restrict__ et,
                          const int* __restrict__ offs, int* __restrict__ cur,
                          int4* __restrict__ edge4) {
    int e = blockIdx.x * blockDim.x + threadIdx.x;
    if (e >= EE) return;
    int r = rowp[e], c = colp[e], t = et[e];
    int pA = offs[c] + atomicAdd(&cur[c], 1);
    edge4[pA] = make_int4(r, t, e, 0);          // dirA: dest=col, src=row
    int pB = offs[NN + r] + atomicAdd(&cur[NN + r], 1);
    edge4[pB] = make_int4(c, t, e, 0);          // dirB: dest=row, src=col
}

// At[k][m] = A[m][k], zero-padded rows k in [K, 128)
__global__ void transpose_A(const float* __restrict__ A, int M, int K,
                            float* __restrict__ At) {
    __shared__ float t[32][33];
    int mb = blockIdx.x * 32, kb = blockIdx.y * 32;
    int tx = threadIdx.x, ty = threadIdx.y;
#pragma unroll
    for (int i = 0; i < 32; i += 8) {
        int m = mb + ty + i, k = kb + tx;
        t[ty + i][tx] = (m < M && k < K) ? A[(size_t)m * K + k] : 0.f;
    }
    __syncthreads();
#pragma unroll
    for (int i = 0; i < 32; i += 8) {
        int k = kb + ty + i, m = mb + tx;
        if (m < M) At[(size_t)k * M + m] = t[tx][ty + i];
    }
}

// Wt[y][k][n] = Wsel_y[n][koff_y + k], zero-padded
__global__ void prep_wt(const float* __restrict__ Wi, const float* __restrict__ Wo,
                        int ldw, int K, float* __restrict__ Wt) {
    int y = blockIdx.y, k = blockIdx.x, n = threadIdx.x;
    const float* W = (y < 2) ? Wi : Wo;
    int koff = (y & 1) ? K : 0;
    Wt[((y * 128) + k) * 128 + n] = (k < K) ? W[n * ldw + koff + k] : 0.f;
}

// Fused 4-projection GEMM (cp.async double-buffered) + fused att-dot epilogue.
__global__ __launch_bounds__(256) void gemm4(
    const float* __restrict__ At, int M, int K,
    const float* __restrict__ Wt,
    const float* __restrict__ ai, const float* __restrict__ ao,
    float* __restrict__ uA, float* __restrict__ vA,
    float* __restrict__ uB, float* __restrict__ vB,
    float* __restrict__ psc)
{
    int y = blockIdx.y;
    const float* att = (y < 2) ? ai : ao;
    float* C = (y == 0) ? uA : (y == 1) ? vA : (y == 2) ? uB : vB;
    const float* Wy = Wt + y * 128 * 128;

    __shared__ float As[2][16][128];
    __shared__ float Bs[2][16][128];

    int m0 = blockIdx.x * 128;
    int tid = threadIdx.x;
    int tx = tid & 15;
    int ty = tid >> 4;
    float acc[8][8] = {};

    int KT = (K + 15) / 16;

#define STAGE_TILE(T, BUF)                                                         \
    {                                                                              \
        int k0 = (T) * 16;                                                         \
        uint32_t sA = s2u(&As[BUF][0][0]);                                         \
        uint32_t sB = s2u(&Bs[BUF][0][0]);                                         \
        _Pragma("unroll")                                                          \
        for (int i = 0; i < 2; i++) {                                              \
            int ch = tid + i * 256;                                                \
            int row = ch >> 5;                                                     \
            int coff = (ch & 31) * 4;                                              \
            uint32_t ok = (m0 + coff < M) ? 16u : 0u;                              \
            const float* ga = At + (size_t)(k0 + row) * M + (ok ? (m0 + coff) : 0);\
            asm volatile("cp.async.cg.shared.global [%0], [%1], 16, %2;"           \
                         :: "r"(sA + (uint32_t)((row * 128 + coff) * 4)),          \
                            "l"(ga), "r"(ok));                                     \
            const float* gb = Wy + (k0 + row) * 128 + coff;                        \
            asm volatile("cp.async.cg.shared.global [%0], [%1], 16;"               \
                         :: "r"(sB + (uint32_t)((row * 128 + coff) * 4)),          \
                            "l"(gb));                                              \
        }                                                                          \
        asm volatile("cp.async.commit_group;");                                    \
    }

    STAGE_TILE(0, 0);

    for (int t = 0; t < KT; t++) {
        int buf = t & 1;
        if (t + 1 < KT) {
            STAGE_TILE(t + 1, buf ^ 1);
            asm volatile("cp.async.wait_group 1;");
        } else {
            asm volatile("cp.async.wait_group 0;");
        }
        __syncthreads();
        const float(*Ab)[128] = As[buf];
        const float(*Bb)[128] = Bs[buf];
#pragma unroll
        for (int k = 0; k < 16; k++) {
            float4 a0 = *(const float4*)&Ab[k][ty * 8];
            float4 a1 = *(const float4*)&Ab[k][ty * 8 + 4];
            float4 b0 = *(const float4*)&Bb[k][tx * 8];
            float4 b1 = *(const float4*)&Bb[k][tx * 8 + 4];
            float av[8] = {a0.x, a0.y, a0.z, a0.w, a1.x, a1.y, a1.z, a1.w};
            float bv[8] = {b0.x, b0.y, b0.z, b0.w, b1.x, b1.y, b1.z, b1.w};
#pragma unroll
            for (int i = 0; i < 8; i++)
#pragma unroll
                for (int j = 0; j < 8; j++)
                    acc[i][j] = fmaf(av[i], bv[j], acc[i][j]);
        }
        __syncthreads();
    }
#undef STAGE_TILE

#pragma unroll
    for (int i = 0; i < 8; i++) {
        int gm = m0 + ty * 8 + i;
        if (gm >= M) continue;
#pragma unroll
        for (int j = 0; j < 8; j += 4) {
            float4 v = make_float4(acc[i][j], acc[i][j + 1], acc[i][j + 2], acc[i][j + 3]);
            *(float4*)&C[(size_t)gm * 128 + tx * 8 + j] = v;
        }
    }

    int h = tx >> 3;
    float attv[8];
#pragma unroll
    for (int j = 0; j < 8; j++) attv[j] = att[tx * 8 + j];
#pragma unroll
    for (int i = 0; i < 8; i++) {
        float pp = 0.f;
#pragma unroll
        for (int j = 0; j < 8; j++) pp = fmaf(attv[j], acc[i][j], pp);
#pragma unroll
        for (int o = 1; o < 8; o <<= 1) pp += __shfl_xor_sync(0xffffffffu, pp, o);
        int gm = m0 + ty * 8 + i;
        if ((tx & 7) == 0 && gm < M)
            atomicAdd(&psc[gm * 8 + y * 2 + h], pp);
    }
}

// C[M x N] = A[M x K] @ W.T (+bias) — entity layer
__global__ __launch_bounds__(256) void gemm_wt(
    const float* __restrict__ A, int lda,
    const float* __restrict__ W, int ldw, int K,
    const float* __restrict__ bias,
    float* __restrict__ C, int ldc, int M)
{
    __shared__ float As[64][17];
    __shared__ float Bs[16][65];
    int m0 = blockIdx.x * 64, n0 = blockIdx.y * 64;
    int tx = threadIdx.x & 15, ty = threadIdx.x >> 4;
    float acc[4][4] = {};
    for (int k0 = 0; k0 < K; k0 += 16) {
#pragma unroll
        for (int i = 0; i < 4; i++) {
            int li = threadIdx.x + i * 256;
            int k = li & 15, m = li >> 4;
            int gm = m0 + m, gk = k0 + k;
            As[m][k] = (gm < M && gk < K) ? A[gm * lda + gk] : 0.f;
        }
#pragma unroll
        for (int i = 0; i < 4; i++) {
            int li = threadIdx.x + i * 256;
            int k = li & 15, n = li >> 4;
            int gk = k0 + k;
            Bs[k][n] = (gk < K) ? W[(n0 + n) * ldw + gk] : 0.f;
        }
        __syncthreads();
#pragma unroll
        for (int k = 0; k < 16; k++) {
            float a[4], b[4];
#pragma unroll
            for (int i = 0; i < 4; i++) a[i] = As[ty * 4 + i][k];
#pragma unroll
            for (int j = 0; j < 4; j++) b[j] = Bs[k][tx * 4 + j];
#pragma unroll
            for (int i = 0; i < 4; i++)
#pragma unroll
                for (int j = 0; j < 4; j++)
                    acc[i][j] = fmaf(a[i], b[j], acc[i][j]);
        }
        __syncthreads();
    }
#pragma unroll
    for (int i = 0; i < 4; i++) {
        int gm = m0 + ty * 4 + i;
        if (gm >= M) continue;
#pragma unroll
        for (int j = 0; j < 4; j++) {
            int gn = n0 + tx * 4 + j;
            C[gm * ldc + gn] = acc[i][j] + bias[gn];
        }
    }
}

// Relation projection for both directions + fused aw reduction (packed output).
__global__ void relproj2(const float* __restrict__ g,
                         const float* __restrict__ Wi, const float* __restrict__ bi,
                         const float* __restrict__ ai,
                         const float* __restrict__ Wo, const float* __restrict__ bo,
                         const float* __restrict__ ao,
                         int ldw, int koff,
                         float* __restrict__ wA, float* __restrict__ wB,
                         float* __restrict__ paw)
{
    int r = blockIdx.x, y = blockIdx.y;
    const float* W = y ? Wo : Wi;
    const float* b = y ? bo : bi;
    const float* att = y ? ao : ai;
    float* wout = y ? wB : wA;
    __shared__ float gs[GS];
    int n = threadIdx.x;
    if (n < GS) gs[n] = g[r * GS + n];
    __syncthreads();
    float acc = b[n];
    const float* wr = W + n * ldw + koff;
#pragma unroll 4
    for (int k = 0; k < GS; k++) acc = fmaf(wr[k], gs[k], acc);
    wout[r * 128 + n] = acc;
    float s = wsum(acc * att[n]);
    __shared__ float sm[4];
    if ((n & 31) == 0) sm[n >> 5] = s;
    __syncthreads();
    if (n == 0) paw[r * 4 + y * 2 + 0] = sm[0] + sm[1];
    if (n == 64) paw[r * 4 + y * 2 + 1] = sm[2] + sm[3];
}

// g_prime: block per relation
__global__ void relproj_out(const float* __restrict__ g, const float* __restrict__ Wr,
                            const float* __restrict__ br, float* __restrict__ out)
{
    int r = blockIdx.x;
    __shared__ float gs[GS];
    int n = threadIdx.x;
    if (n < GS) gs[n] = g[r * GS + n];
    __syncthreads();
    float acc = br[n];
    const float* wr = Wr + n * GS;
#pragma unroll 4
    for (int k = 0; k < GS; k++) acc = fmaf(wr[k], gs[k], acc);
    out[r * 128 + n] = acc;
}

// Fused pass A for both directions: one thread per edge, packed-scalar gathers.
__global__ __launch_bounds__(256) void pass_a2(
    const int* __restrict__ rowp, const int* __restrict__ colp, const int* __restrict__ et,
    const float* __restrict__ psc, const float* __restrict__ paw,
    float* __restrict__ ebA, float* __restrict__ ebB,
    float* __restrict__ denA, float* __restrict__ denB)
{
    int e = blockIdx.x * blockDim.x + threadIdx.x;
    if (e >= EE) return;
    int r = rowp[e], c = colp[e], t = et[e];
    float4 r0 = *(const float4*)&psc[r * 8];
    float4 r1 = *(const float4*)&psc[r * 8 + 4];
    float4 c0 = *(const float4*)&psc[c * 8];
    float4 c1 = *(const float4*)&psc[c * 8 + 4];
    float4 aw = *(const float4*)&paw[t * 4];

    float a0 = r0.x + c0.z + aw.x;
    float a1 = r0.y + c0.w + aw.y;
    float b0 = c1.x + r1.z + aw.z;
    float b1 = c1.y + r1.w + aw.w;

    a0 = (a0 > 0.f) ? a0 : kNEG * a0;
    a1 = (a1 > 0.f) ? a1 : kNEG * a1;
    b0 = (b0 > 0.f) ? b0 : kNEG * b0;
    b1 = (b1 > 0.f) ? b1 : kNEG * b1;
    float ea0 = expf(a0), ea1 = expf(a1), eb0 = expf(b0), eb1 = expf(b1);
    *(float2*)&ebA[e * 2] = make_float2(ea0, ea1);
    *(float2*)&ebB[e * 2] = make_float2(eb0, eb1);
    atomicAdd(&denA[r * 2 + 0], ea0);
    atomicAdd(&denA[r * 2 + 1], ea1);
    atomicAdd(&denB[c * 2 + 0], eb0);
    atomicAdd(&denB[c * 2 + 1], eb1);
}

// CSR pass B: warp per destination node, per direction. No atomics; plain stores.
// y=0: dirA (dest=col, edges at offs[d]; src=row)  y=1: dirB (dest=row, offs[NN+d])
__global__ __launch_bounds__(256) void pass_b_csr(
    const int4* __restrict__ edge4,
    const int* __restrict__ offs, const int* __restrict__ counts,
    const float* __restrict__ uA, const float* __restrict__ wA,
    const float* __restrict__ ebA, const float* __restrict__ denA,
    float* __restrict__ accA, float* __restrict__ salA,
    const float* __restrict__ uB, const float* __restrict__ wB,
    const float* __restrict__ ebB, const float* __restrict__ denB,
    float* __restrict__ accB, float* __restrict__ salB)
{
    int y = blockIdx.y;
    const float* u = y ? uB : uA;
    const float* w = y ? wB : wA;
    const float* eb = y ? ebB : ebA;
    const float* den = y ? denB : denA;
    float* acc = y ? accB : accA;
    float* sal = y ? salB : salA;

    int d = blockIdx.x * 8 + (threadIdx.x >> 5);
    if (d >= NN) return;
    int l = threadIdx.x & 31;
    int h = l >> 4;
    int slot = y ? NN + d : d;
    int base = offs[slot];
    int cnt = counts[slot];

    float4 a4 = make_float4(0.f, 0.f, 0.f, 0.f);
    float sa = 0.f;

    for (int i = 0; i < cnt; i++) {
        int4 e4 = edge4[base + i];
        int s = e4.x, t = e4.y, e = e4.z;
        float alpha = eb[e * 2 + h] / den[s * 2 + h];
        float4 uv = ((const float4*)(u + (size_t)s * 128))[l];
        float4 wv = ((const float4*)(w + (size_t)t * 128))[l];
        a4.x = fmaf(alpha, uv.x + wv.x, a4.x);
        a4.y = fmaf(alpha, uv.y + wv.y, a4.y);
        a4.z = fmaf(alpha, uv.z + wv.z, a4.z);
        a4.w = fmaf(alpha, uv.w + wv.w, a4.w);
        sa += alpha;
    }
    *(float4*)&acc[(size_t)d * 128 + l * 4] = a4;
    if (l == 0) sal[d * 2 + 0] = sa;
    if (l == 16) sal[d * 2 + 1] = sa;
}

// out = l2norm_per_head(leaky(0.5*(accA + salA*vA) + 0.5*(accB + salB*vB)))
__global__ void combine(const float* __restrict__ accA, const float* __restrict__ salA,
                        const float* __restrict__ vA,
                        const float* __restrict__ accB, const float* __restrict__ salB,
                        const float* __restrict__ vB,
                        float* __restrict__ out)
{
    int i = blockIdx.x, j = threadIdx.x;
    int h = j >> 6;
    float a = accA[i * 128 + j] + salA[i * 2 + h] * vA[i * 128 + j];
    float b = accB[i * 128 + j] + salB[i * 2 + h] * vB[i * 128 + j];
    float v = 0.5f * (a + b);
    v = (v > 0.f) ? v : kNEG * v;
    float s = wsum(v * v);
    __shared__ float sm[4];
    if ((j & 31) == 0) sm[j >> 5] = s;
    __syncthreads();
    float tot = sm[h * 2] + sm[h * 2 + 1];
    out[i * 128 + j] = v / fmaxf(sqrtf(tot), kEPS);
}

// h_prime = l2norm_128(ent broadcast over heads + h)
__global__ void final_k(const float* __restrict__ ent, const float* __restrict__ h,
                        float* __restrict__ out)
{
    int i = blockIdx.x, j = threadIdx.x;
    float v = ent[i * 64 + (j & 63)] + h[i * 128 + j];
    float s = wsum(v * v);
    __shared__ float sm[4];
    if ((j & 31) == 0) sm[j >> 5] = s;
    __syncthreads();
    float tot = sm[0] + sm[1] + sm[2] + sm[3];
    out[i * 128 + j] = v / fmaxf(sqrtf(tot), kEPS);
}

// ------------------------- host orchestration -------------------------
namespace {
struct Ptrs {
    float *xn, *At, *Wt, *uA, *vA, *uB, *vB, *accA, *accB, *salA, *salB, *h, *ent, *wA, *wB;
    float *psc, *paw, *ebA, *ebB, *denA, *denB;
    int *counts, *cur, *offs, *csum;
    int4 *edge4;
};

static void get_ptrs(Ptrs& p) {
    cudaGetSymbolAddress((void**)&p.xn, d_xn);
    cudaGetSymbolAddress((void**)&p.At, d_At);
    cudaGetSymbolAddress((void**)&p.Wt, d_Wt);
    cudaGetSymbolAddress((void**)&p.uA, d_uA);
    cudaGetSymbolAddress((void**)&p.vA, d_vA);
    cudaGetSymbolAddress((void**)&p.uB, d_uB);
    cudaGetSymbolAddress((void**)&p.vB, d_vB);
    cudaGetSymbolAddress((void**)&p.accA, d_accA);
    cudaGetSymbolAddress((void**)&p.accB, d_accB);
    cudaGetSymbolAddress((void**)&p.salA, d_salA);
    cudaGetSymbolAddress((void**)&p.salB, d_salB);
    cudaGetSymbolAddress((void**)&p.h, d_h);
    cudaGetSymbolAddress((void**)&p.ent, d_ent);
    cudaGetSymbolAddress((void**)&p.wA, d_wA);
    cudaGetSymbolAddress((void**)&p.wB, d_wB);
    cudaGetSymbolAddress((void**)&p.psc, d_psc);
    cudaGetSymbolAddress((void**)&p.paw, d_paw);
    cudaGetSymbolAddress((void**)&p.ebA, d_ebA);
    cudaGetSymbolAddress((void**)&p.ebB, d_ebB);
    cudaGetSymbolAddress((void**)&p.denA, d_denA);
    cudaGetSymbolAddress((void**)&p.denB, d_denB);
    cudaGetSymbolAddress((void**)&p.counts, d_counts);
    cudaGetSymbolAddress((void**)&p.cur, d_cur);
    cudaGetSymbolAddress((void**)&p.offs, d_offs);
    cudaGetSymbolAddress((void**)&p.csum, d_csum);
    cudaGetSymbolAddress((void**)&p.edge4, d_edge4);
}

static void run_layer(const Ptrs& p,
                      const float* A, int K, int ldw,
                      const float* Wi, const float* bi, const float* ai,
                      const float* Wo, const float* bo, const float* ao,
                      const float* g,
                      const int* rowp, const int* colp, const int* et,
                      float* outH)
{
    transpose_A<<<dim3((NN + 31) / 32, 4), dim3(32, 8)>>>(A, NN, K, p.At);
    prep_wt<<<dim3(128, 4), 128>>>(Wi, Wo, ldw, K, p.Wt);
    cudaMemsetAsync(p.psc, 0, NN * 8 * sizeof(float));
    dim3 gg((NN + 127) / 128, 4);
    gemm4<<<gg, 256>>>(p.At, NN, K, p.Wt, ai, ao,
                       p.uA, p.vA, p.uB, p.vB, p.psc);
    dim3 gr(RR, 2);
    relproj2<<<gr, 128>>>(g, Wi, bi, ai, Wo, bo, ao, ldw, 2 * K,
                          p.wA, p.wB, p.paw);
    cudaMemsetAsync(p.denA, 0, NN * 2 * sizeof(float));
    cudaMemsetAsync(p.denB, 0, NN * 2 * sizeof(float));
    pass_a2<<<(EE + 255) / 256, 256>>>(rowp, colp, et, p.psc, p.paw,
                                       p.ebA, p.ebB, p.denA, p.denB);
    dim3 gb((NN + 7) / 8, 2);
    pass_b_csr<<<gb, 256>>>(p.edge4, p.offs, p.counts,
                            p.uA, p.wA, p.ebA, p.denA, p.accA, p.salA,
                            p.uB, p.wB, p.ebB, p.denB, p.accB, p.salB);
    combine<<<NN, 128>>>(p.accA, p.salA, p.vA, p.accB, p.salB, p.vB, outH);
}
}  // namespace

extern "C" void kernel_launch(void* const* d_in, const int* in_sizes, int n_in,
                              void* d_out, int out_size)
{
    const float* x   = (const float*)d_in[0];
    const float* g   = (const float*)d_in[1];
    const int*   ei  = (const int*)d_in[2];
    const int*   et  = (const int*)d_in[3];
    const float* W1i = (const float*)d_in[4];
    const float* b1i = (const float*)d_in[5];
    const float* a1i = (const float*)d_in[6];
    const float* W1o = (const float*)d_in[7];
    const float* b1o = (const float*)d_in[8];
    const float* a1o = (const float*)d_in[9];
    const float* W2i = (const float*)d_in[10];
    const float* b2i = (const float*)d_in[11];
    const float* a2i = (const float*)d_in[12];
    const float* W2o = (const float*)d_in[13];
    const float* b2o = (const float*)d_in[14];
    const float* a2o = (const float*)d_in[15];
    const float* We  = (const float*)d_in[16];
    const float* be  = (const float*)d_in[17];
    const float* Wr  = (const float*)d_in[18];
    const float* br  = (const float*)d_in[19];
    float* out = (float*)d_out;

    const int* rowp = ei;
    const int* colp = ei + EE;

    Ptrs p;
    get_ptrs(p);

    // edge counting sort (once per call; shared by both layers & directions)
    const int M2 = 2 * NN;
    const int NB = (M2 + 511) / 512;
    cudaMemsetAsync(p.counts, 0, M2 * sizeof(int));
    cudaMemsetAsync(p.cur, 0, M2 * sizeof(int));
    hist_k<<<(EE + 255) / 256, 256>>>(rowp, colp, p.counts);
    scan1<<<NB, 512>>>(p.counts, p.offs, p.csum, M2);
    scan2<<<1, 256>>>(p.csum, NB);
    scan3<<<(M2 + 255) / 256, 256>>>(p.offs, p.csum, M2);
    scatter_k<<<(EE + 255) / 256, 256>>>(rowp, colp, et, p.offs, p.cur, p.edge4);

    norm_x<<<NN, 128>>>(x, p.xn);

    // layer 1: input xn [NN,100]
    run_layer(p, p.xn, XS, 2 * XS + GS,
              W1i, b1i, a1i, W1o, b1o, a1o, g, rowp, colp, et, p.h);

    // layer 2: input h [NN,128]
    run_layer(p, p.h, 128, 2 * 128 + GS,
              W2i, b2i, a2i, W2o, b2o, a2o, g, rowp, colp, et, p.h);

    // entity layer
    dim3 ge((NN + 63) / 64, 1);
    gemm_wt<<<ge, 256>>>(p.xn, XS, We, XS, XS, be, p.ent, 64, NN);

    final_k<<<NN, 128>>>(p.ent, p.h, out);
    relproj_out<<<RR, 128>>>(g, Wr, br, out + NN * 128);
}

// round 11
// speedup vs baseline: 1.3226x; 1.0611x over previous
#include <cuda_runtime.h>
#include <math.h>
#include <stdint.h>

#define NN 50000
#define EE 400000
#define RR 500
#define XS 100
#define GS 100

static __device__ __constant__ float kNEG = 0.01f;
static __device__ __constant__ float kEPS = 1e-12f;

// ------------------------- scratch (device globals) -------------------------
__device__ float d_xn[NN * XS];
__device__ float d_At[128 * NN];        // k-major transposed activations (zero-padded)
__device__ float d_Wt[4 * 128 * 128];   // k-major weight slices per projection y
__device__ float d_uA[NN * 128];
__device__ float d_vA[NN * 128];
__device__ float d_uB[NN * 128];
__device__ float d_vB[NN * 128];
__device__ float d_accA[NN * 128];
__device__ float d_accB[NN * 128];
__device__ float d_salA[NN * 2];
__device__ float d_salB[NN * 2];
__device__ float d_h[NN * 128];
__device__ float d_ent[NN * 64];
__device__ float d_wA[RR * 128];
__device__ float d_wB[RR * 128];
__device__ float d_psc[NN * 8];
__device__ float d_paw[RR * 4];
__device__ float d_ebS[2 * EE * 2];     // exp values in SORTED order (dirA:[0,EE), dirB:[EE,2EE))
__device__ float d_alphaS[2 * EE * 2];  // normalized alphas in sorted order
__device__ float d_denA[NN * 2];
__device__ float d_denB[NN * 2];
// edge sort scratch: [0,NN) = counts by col (dirA dest), [NN,2NN) by row (dirB dest)
__device__ int d_counts[2 * NN];
__device__ int d_cur[2 * NN];
__device__ int d_offs[2 * NN];
__device__ int d_csum[256];
__device__ int2 d_edge2[2 * EE];        // sorted edge payload: {src, type}
__device__ int d_posA[EE];
__device__ int d_posB[EE];

// ------------------------- helpers -------------------------
__device__ __forceinline__ float wsum(float v) {
#pragma unroll
    for (int o = 16; o > 0; o >>= 1) v += __shfl_xor_sync(0xffffffffu, v, o);
    return v;
}

__device__ __forceinline__ uint32_t s2u(const void* p) {
    return (uint32_t)__cvta_generic_to_shared(p);
}

// L2-normalize rows of x [NN, XS]
__global__ void norm_x(const float* __restrict__ x, float* __restrict__ xn) {
    int i = blockIdx.x;
    int j = threadIdx.x;
    float v = (j < XS) ? x[i * XS + j] : 0.f;
    float s = wsum(v * v);
    __shared__ float sm[4];
    if ((j & 31) == 0) sm[j >> 5] = s;
    __syncthreads();
    float tot = sm[0] + sm[1] + sm[2] + sm[3];
    if (j < XS) xn[i * XS + j] = v / fmaxf(sqrtf(tot), kEPS);
}

// ------------------------- edge counting sort -------------------------
__global__ void hist_k(const int* __restrict__ rowp, const int* __restrict__ colp,
                       int* __restrict__ counts) {
    int e = blockIdx.x * blockDim.x + threadIdx.x;
    if (e >= EE) return;
    atomicAdd(&counts[colp[e]], 1);
    atomicAdd(&counts[NN + rowp[e]], 1);
}

__global__ void scan1(const int* __restrict__ counts, int* __restrict__ offs,
                      int* __restrict__ csum, int M) {
    __shared__ int sm[512];
    int i = threadIdx.x, g = blockIdx.x * 512 + i;
    int v = (g < M) ? counts[g] : 0;
    sm[i] = v;
    __syncthreads();
    for (int o = 1; o < 512; o <<= 1) {
        int t = (i >= o) ? sm[i - o] : 0;
        __syncthreads();
        sm[i] += t;
        __syncthreads();
    }
    if (g < M) offs[g] = sm[i] - v;
    if (i == 511) csum[blockIdx.x] = sm[511];
}

__global__ void scan2(int* __restrict__ csum, int NB) {
    __shared__ int sm[256];
    int i = threadIdx.x;
    int v = (i < NB) ? csum[i] : 0;
    sm[i] = v;
    __syncthreads();
    for (int o = 1; o < 256; o <<= 1) {
        int t = (i >= o) ? sm[i - o] : 0;
        __syncthreads();
        sm[i] += t;
        __syncthreads();
    }
    if (i < NB) csum[i] = sm[i] - v;
}

__global__ void scan3(int* __restrict__ offs, const int* __restrict__ csum, int M) {
    int g = blockIdx.x * 256 + threadIdx.x;
    if (g < M) offs[g] += csum[g >> 9];
}

__global__ void scatter_k(const int* __restrict__ rowp, const int* __restrict__ colp,
                          const int* __restrict__ et,
                          const int* __restrict__ offs, int* __restrict__ cur,
                          int2* __restrict__ edge2,
                          int* __restrict__ posA, int* __restrict__ posB) {
    int e = blockIdx.x * blockDim.x + threadIdx.x;
    if (e >= EE) return;
    int r = rowp[e], c = colp[e], t = et[e];
    int pA = offs[c] + atomicAdd(&cur[c], 1);
    edge2[pA] = make_int2(r, t);               // dirA: dest=col, src=row
    posA[e] = pA;
    int pB = offs[NN + r] + atomicAdd(&cur[NN + r], 1);   // pB in [EE, 2EE)
    edge2[pB] = make_int2(c, t);               // dirB: dest=row, src=col
    posB[e] = pB;
}

// At[k][m] = A[m][k], zero-padded rows k in [K, 128)
__global__ void transpose_A(const float* __restrict__ A, int M, int K,
                            float* __restrict__ At) {
    __shared__ float t[32][33];
    int mb = blockIdx.x * 32, kb = blockIdx.y * 32;
    int tx = threadIdx.x, ty = threadIdx.y;
#pragma unroll
    for (int i = 0; i < 32; i += 8) {
        int m = mb + ty + i, k = kb + tx;
        t[ty + i][tx] = (m < M && k < K) ? A[(size_t)m * K + k] : 0.f;
    }
    __syncthreads();
#pragma unroll
    for (int i = 0; i < 32; i += 8) {
        int k = kb + ty + i, m = mb + tx;
        if (m < M) At[(size_t)k * M + m] = t[tx][ty + i];
    }
}

// Wt[y][k][n] = Wsel_y[n][koff_y + k], zero-padded
__global__ void prep_wt(const float* __restrict__ Wi, const float* __restrict__ Wo,
                        int ldw, int K, float* __restrict__ Wt) {
    int y = blockIdx.y, k = blockIdx.x, n = threadIdx.x;
    const float* W = (y < 2) ? Wi : Wo;
    int koff = (y & 1) ? K : 0;
    Wt[((y * 128) + k) * 128 + n] = (k < K) ? W[n * ldw + koff + k] : 0.f;
}

// Fused 4-projection GEMM (cp.async double-buffered) + fused att-dot epilogue.
__global__ __launch_bounds__(256) void gemm4(
    const float* __restrict__ At, int M, int K,
    const float* __restrict__ Wt,
    const float* __restrict__ ai, const float* __restrict__ ao,
    float* __restrict__ uA, float* __restrict__ vA,
    float* __restrict__ uB, float* __restrict__ vB,
    float* __restrict__ psc)
{
    int y = blockIdx.y;
    const float* att = (y < 2) ? ai : ao;
    float* C = (y == 0) ? uA : (y == 1) ? vA : (y == 2) ? uB : vB;
    const float* Wy = Wt + y * 128 * 128;

    __shared__ float As[2][16][128];
    __shared__ float Bs[2][16][128];

    int m0 = blockIdx.x * 128;
    int tid = threadIdx.x;
    int tx = tid & 15;
    int ty = tid >> 4;
    float acc[8][8] = {};

    int KT = (K + 15) / 16;

#define STAGE_TILE(T, BUF)                                                         \
    {                                                                              \
        int k0 = (T) * 16;                                                         \
        uint32_t sA = s2u(&As[BUF][0][0]);                                         \
        uint32_t sB = s2u(&Bs[BUF][0][0]);                                         \
        _Pragma("unroll")                                                          \
        for (int i = 0; i < 2; i++) {                                              \
            int ch = tid + i * 256;                                                \
            int row = ch >> 5;                                                     \
            int coff = (ch & 31) * 4;                                              \
            uint32_t ok = (m0 + coff < M) ? 16u : 0u;                              \
            const float* ga = At + (size_t)(k0 + row) * M + (ok ? (m0 + coff) : 0);\
            asm volatile("cp.async.cg.shared.global [%0], [%1], 16, %2;"           \
                         :: "r"(sA + (uint32_t)((row * 128 + coff) * 4)),          \
                            "l"(ga), "r"(ok));                                     \
            const float* gb = Wy + (k0 + row) * 128 + coff;                        \
            asm volatile("cp.async.cg.shared.global [%0], [%1], 16;"               \
                         :: "r"(sB + (uint32_t)((row * 128 + coff) * 4)),          \
                            "l"(gb));                                              \
        }                                                                          \
        asm volatile("cp.async.commit_group;");                                    \
    }

    STAGE_TILE(0, 0);

    for (int t = 0; t < KT; t++) {
        int buf = t & 1;
        if (t + 1 < KT) {
            STAGE_TILE(t + 1, buf ^ 1);
            asm volatile("cp.async.wait_group 1;");
        } else {
            asm volatile("cp.async.wait_group 0;");
        }
        __syncthreads();
        const float(*Ab)[128] = As[buf];
        const float(*Bb)[128] = Bs[buf];
#pragma unroll
        for (int k = 0; k < 16; k++) {
            float4 a0 = *(const float4*)&Ab[k][ty * 8];
            float4 a1 = *(const float4*)&Ab[k][ty * 8 + 4];
            float4 b0 = *(const float4*)&Bb[k][tx * 8];
            float4 b1 = *(const float4*)&Bb[k][tx * 8 + 4];
            float av[8] = {a0.x, a0.y, a0.z, a0.w, a1.x, a1.y, a1.z, a1.w};
            float bv[8] = {b0.x, b0.y, b0.z, b0.w, b1.x, b1.y, b1.z, b1.w};
#pragma unroll
            for (int i = 0; i < 8; i++)
#pragma unroll
                for (int j = 0; j < 8; j++)
                    acc[i][j] = fmaf(av[i], bv[j], acc[i][j]);
        }
        __syncthreads();
    }
#undef STAGE_TILE

#pragma unroll
    for (int i = 0; i < 8; i++) {
        int gm = m0 + ty * 8 + i;
        if (gm >= M) continue;
#pragma unroll
        for (int j = 0; j < 8; j += 4) {
            float4 v = make_float4(acc[i][j], acc[i][j + 1], acc[i][j + 2], acc[i][j + 3]);
            *(float4*)&C[(size_t)gm * 128 + tx * 8 + j] = v;
        }
    }

    int h = tx >> 3;
    float attv[8];
#pragma unroll
    for (int j = 0; j < 8; j++) attv[j] = att[tx * 8 + j];
#pragma unroll
    for (int i = 0; i < 8; i++) {
        float pp = 0.f;
#pragma unroll
        for (int j = 0; j < 8; j++) pp = fmaf(attv[j], acc[i][j], pp);
#pragma unroll
        for (int o = 1; o < 8; o <<= 1) pp += __shfl_xor_sync(0xffffffffu, pp, o);
        int gm = m0 + ty * 8 + i;
        if ((tx & 7) == 0 && gm < M)
            atomicAdd(&psc[gm * 8 + y * 2 + h], pp);
    }
}

// C[M x N] = A[M x K] @ W.T (+bias) — entity layer
__global__ __launch_bounds__(256) void gemm_wt(
    const float* __restrict__ A, int lda,
    const float* __restrict__ W, int ldw, int K,
    const float* __restrict__ bias,
    float* __restrict__ C, int ldc, int M)
{
    __shared__ float As[64][17];
    __shared__ float Bs[16][65];
    int m0 = blockIdx.x * 64, n0 = blockIdx.y * 64;
    int tx = threadIdx.x & 15, ty = threadIdx.x >> 4;
    float acc[4][4] = {};
    for (int k0 = 0; k0 < K; k0 += 16) {
#pragma unroll
        for (int i = 0; i < 4; i++) {
            int li = threadIdx.x + i * 256;
            int k = li & 15, m = li >> 4;
            int gm = m0 + m, gk = k0 + k;
            As[m][k] = (gm < M && gk < K) ? A[gm * lda + gk] : 0.f;
        }
#pragma unroll
        for (int i = 0; i < 4; i++) {
            int li = threadIdx.x + i * 256;
            int k = li & 15, n = li >> 4;
            int gk = k0 + k;
            Bs[k][n] = (gk < K) ? W[(n0 + n) * ldw + gk] : 0.f;
        }
        __syncthreads();
#pragma unroll
        for (int k = 0; k < 16; k++) {
            float a[4], b[4];
#pragma unroll
            for (int i = 0; i < 4; i++) a[i] = As[ty * 4 + i][k];
#pragma unroll
            for (int j = 0; j < 4; j++) b[j] = Bs[k][tx * 4 + j];
#pragma unroll
            for (int i = 0; i < 4; i++)
#pragma unroll
                for (int j = 0; j < 4; j++)
                    acc[i][j] = fmaf(a[i], b[j], acc[i][j]);
        }
        __syncthreads();
    }
#pragma unroll
    for (int i = 0; i < 4; i++) {
        int gm = m0 + ty * 4 + i;
        if (gm >= M) continue;
#pragma unroll
        for (int j = 0; j < 4; j++) {
            int gn = n0 + tx * 4 + j;
            C[gm * ldc + gn] = acc[i][j] + bias[gn];
        }
    }
}

// Relation projection for both directions + fused aw reduction (packed output).
__global__ void relproj2(const float* __restrict__ g,
                         const float* __restrict__ Wi, const float* __restrict__ bi,
                         const float* __restrict__ ai,
                         const float* __restrict__ Wo, const float* __restrict__ bo,
                         const float* __restrict__ ao,
                         int ldw, int koff,
                         float* __restrict__ wA, float* __restrict__ wB,
                         float* __restrict__ paw)
{
    int r = blockIdx.x, y = blockIdx.y;
    const float* W = y ? Wo : Wi;
    const float* b = y ? bo : bi;
    const float* att = y ? ao : ai;
    float* wout = y ? wB : wA;
    __shared__ float gs[GS];
    int n = threadIdx.x;
    if (n < GS) gs[n] = g[r * GS + n];
    __syncthreads();
    float acc = b[n];
    const float* wr = W + n * ldw + koff;
#pragma unroll 4
    for (int k = 0; k < GS; k++) acc = fmaf(wr[k], gs[k], acc);
    wout[r * 128 + n] = acc;
    float s = wsum(acc * att[n]);
    __shared__ float sm[4];
    if ((n & 31) == 0) sm[n >> 5] = s;
    __syncthreads();
    if (n == 0) paw[r * 4 + y * 2 + 0] = sm[0] + sm[1];
    if (n == 64) paw[r * 4 + y * 2 + 1] = sm[2] + sm[3];
}

// g_prime: block per relation
__global__ void relproj_out(const float* __restrict__ g, const float* __restrict__ Wr,
                            const float* __restrict__ br, float* __restrict__ out)
{
    int r = blockIdx.x;
    __shared__ float gs[GS];
    int n = threadIdx.x;
    if (n < GS) gs[n] = g[r * GS + n];
    __syncthreads();
    float acc = br[n];
    const float* wr = Wr + n * GS;
#pragma unroll 4
    for (int k = 0; k < GS; k++) acc = fmaf(wr[k], gs[k], acc);
    out[r * 128 + n] = acc;
}

// Fused pass A: one thread per edge; exp values written to SORTED positions.
__global__ __launch_bounds__(256) void pass_a2(
    const int* __restrict__ rowp, const int* __restrict__ colp, const int* __restrict__ et,
    const int* __restrict__ posA, const int* __restrict__ posB,
    const float* __restrict__ psc, const float* __restrict__ paw,
    float* __restrict__ ebS,
    float* __restrict__ denA, float* __restrict__ denB)
{
    int e = blockIdx.x * blockDim.x + threadIdx.x;
    if (e >= EE) return;
    int r = rowp[e], c = colp[e], t = et[e];
    float4 r0 = *(const float4*)&psc[r * 8];
    float4 r1 = *(const float4*)&psc[r * 8 + 4];
    float4 c0 = *(const float4*)&psc[c * 8];
    float4 c1 = *(const float4*)&psc[c * 8 + 4];
    float4 aw = *(const float4*)&paw[t * 4];

    float a0 = r0.x + c0.z + aw.x;
    float a1 = r0.y + c0.w + aw.y;
    float b0 = c1.x + r1.z + aw.z;
    float b1 = c1.y + r1.w + aw.w;

    a0 = (a0 > 0.f) ? a0 : kNEG * a0;
    a1 = (a1 > 0.f) ? a1 : kNEG * a1;
    b0 = (b0 > 0.f) ? b0 : kNEG * b0;
    b1 = (b1 > 0.f) ? b1 : kNEG * b1;
    float ea0 = expf(a0), ea1 = expf(a1), eb0 = expf(b0), eb1 = expf(b1);
    *(float2*)&ebS[(size_t)posA[e] * 2] = make_float2(ea0, ea1);
    *(float2*)&ebS[(size_t)posB[e] * 2] = make_float2(eb0, eb1);
    atomicAdd(&denA[r * 2 + 0], ea0);
    atomicAdd(&denA[r * 2 + 1], ea1);
    atomicAdd(&denB[c * 2 + 0], eb0);
    atomicAdd(&denB[c * 2 + 1], eb1);
}

// Materialize normalized alphas in sorted order (flat, high-MLP).
__global__ __launch_bounds__(256) void alpha_k(
    const int2* __restrict__ edge2, const float* __restrict__ ebS,
    const float* __restrict__ denA, const float* __restrict__ denB,
    float* __restrict__ alphaS)
{
    int p = blockIdx.x * blockDim.x + threadIdx.x;
    if (p >= 2 * EE) return;
    int s = edge2[p].x;
    const float* den = (p < EE) ? denA : denB;
    float2 eb = *(const float2*)&ebS[(size_t)p * 2];
    float2 al;
    al.x = eb.x / den[s * 2 + 0];
    al.y = eb.y / den[s * 2 + 1];
    *(float2*)&alphaS[(size_t)p * 2] = al;
}

// CSR pass B: warp per destination node per direction; 2-way unrolled chain.
__global__ __launch_bounds__(256) void pass_b_csr(
    const int2* __restrict__ edge2, const float* __restrict__ alphaS,
    const int* __restrict__ offs, const int* __restrict__ counts,
    const float* __restrict__ uA, const float* __restrict__ wA,
    float* __restrict__ accA, float* __restrict__ salA,
    const float* __restrict__ uB, const float* __restrict__ wB,
    float* __restrict__ accB, float* __restrict__ salB)
{
    int y = blockIdx.y;
    const float* u = y ? uB : uA;
    const float* w = y ? wB : wA;
    float* acc = y ? accB : accA;
    float* sal = y ? salB : salA;

    int d = blockIdx.x * 8 + (threadIdx.x >> 5);
    if (d >= NN) return;
    int l = threadIdx.x & 31;
    int h = l >> 4;
    int slot = y ? NN + d : d;
    int base = offs[slot];
    int cnt = counts[slot];

    float4 a0 = make_float4(0.f, 0.f, 0.f, 0.f);
    float4 a1 = make_float4(0.f, 0.f, 0.f, 0.f);
    float s0 = 0.f, s1 = 0.f;

    int i = 0;
    for (; i + 1 < cnt; i += 2) {
        int2 eA = edge2[base + i];
        int2 eB = edge2[base + i + 1];
        float alA = alphaS[(size_t)(base + i) * 2 + h];
        float alB = alphaS[(size_t)(base + i + 1) * 2 + h];
        float4 u0 = ((const float4*)(u + (size_t)eA.x * 128))[l];
        float4 w0 = ((const float4*)(w + (size_t)eA.y * 128))[l];
        float4 u1 = ((const float4*)(u + (size_t)eB.x * 128))[l];
        float4 w1 = ((const float4*)(w + (size_t)eB.y * 128))[l];
        a0.x = fmaf(alA, u0.x + w0.x, a0.x);
        a0.y = fmaf(alA, u0.y + w0.y, a0.y);
        a0.z = fmaf(alA, u0.z + w0.z, a0.z);
        a0.w = fmaf(alA, u0.w + w0.w, a0.w);
        a1.x = fmaf(alB, u1.x + w1.x, a1.x);
        a1.y = fmaf(alB, u1.y + w1.y, a1.y);
        a1.z = fmaf(alB, u1.z + w1.z, a1.z);
        a1.w = fmaf(alB, u1.w + w1.w, a1.w);
        s0 += alA;
        s1 += alB;
    }
    if (i < cnt) {
        int2 eA = edge2[base + i];
        float alA = alphaS[(size_t)(base + i) * 2 + h];
        float4 u0 = ((const float4*)(u + (size_t)eA.x * 128))[l];
        float4 w0 = ((const float4*)(w + (size_t)eA.y * 128))[l];
        a0.x = fmaf(alA, u0.x + w0.x, a0.x);
        a0.y = fmaf(alA, u0.y + w0.y, a0.y);
        a0.z = fmaf(alA, u0.z + w0.z, a0.z);
        a0.w = fmaf(alA, u0.w + w0.w, a0.w);
        s0 += alA;
    }
    a0.x += a1.x; a0.y += a1.y; a0.z += a1.z; a0.w += a1.w;
    s0 += s1;
    *(float4*)&acc[(size_t)d * 128 + l * 4] = a0;
    if (l == 0) sal[d * 2 + 0] = s0;
    if (l == 16) sal[d * 2 + 1] = s0;
}

// out = l2norm_per_head(leaky(0.5*(accA + salA*vA) + 0.5*(accB + salB*vB)))
__global__ void combine(const float* __restrict__ accA, const float* __restrict__ salA,
                        const float* __restrict__ vA,
                        const float* __restrict__ accB, const float* __restrict__ salB,
                        const float* __restrict__ vB,
                        float* __restrict__ out)
{
    int i = blockIdx.x, j = threadIdx.x;
    int h = j >> 6;
    float a = accA[i * 128 + j] + salA[i * 2 + h] * vA[i * 128 + j];
    float b = accB[i * 128 + j] + salB[i * 2 + h] * vB[i * 128 + j];
    float v = 0.5f * (a + b);
    v = (v > 0.f) ? v : kNEG * v;
    float s = wsum(v * v);
    __shared__ float sm[4];
    if ((j & 31) == 0) sm[j >> 5] = s;
    __syncthreads();
    float tot = sm[h * 2] + sm[h * 2 + 1];
    out[i * 128 + j] = v / fmaxf(sqrtf(tot), kEPS);
}

// h_prime = l2norm_128(ent broadcast over heads + h)
__global__ void final_k(const float* __restrict__ ent, const float* __restrict__ h,
                        float* __restrict__ out)
{
    int i = blockIdx.x, j = threadIdx.x;
    float v = ent[i * 64 + (j & 63)] + h[i * 128 + j];
    float s = wsum(v * v);
    __shared__ float sm[4];
    if ((j & 31) == 0) sm[j >> 5] = s;
    __syncthreads();
    float tot = sm[0] + sm[1] + sm[2] + sm[3];
    out[i * 128 + j] = v / fmaxf(sqrtf(tot), kEPS);
}

// ------------------------- host orchestration -------------------------
namespace {
struct Ptrs {
    float *xn, *At, *Wt, *uA, *vA, *uB, *vB, *accA, *accB, *salA, *salB, *h, *ent, *wA, *wB;
    float *psc, *paw, *ebS, *alphaS, *denA, *denB;
    int *counts, *cur, *offs, *csum, *posA, *posB;
    int2 *edge2;
};

static void get_ptrs(Ptrs& p) {
    cudaGetSymbolAddress((void**)&p.xn, d_xn);
    cudaGetSymbolAddress((void**)&p.At, d_At);
    cudaGetSymbolAddress((void**)&p.Wt, d_Wt);
    cudaGetSymbolAddress((void**)&p.uA, d_uA);
    cudaGetSymbolAddress((void**)&p.vA, d_vA);
    cudaGetSymbolAddress((void**)&p.uB, d_uB);
    cudaGetSymbolAddress((void**)&p.vB, d_vB);
    cudaGetSymbolAddress((void**)&p.accA, d_accA);
    cudaGetSymbolAddress((void**)&p.accB, d_accB);
    cudaGetSymbolAddress((void**)&p.salA, d_salA);
    cudaGetSymbolAddress((void**)&p.salB, d_salB);
    cudaGetSymbolAddress((void**)&p.h, d_h);
    cudaGetSymbolAddress((void**)&p.ent, d_ent);
    cudaGetSymbolAddress((void**)&p.wA, d_wA);
    cudaGetSymbolAddress((void**)&p.wB, d_wB);
    cudaGetSymbolAddress((void**)&p.psc, d_psc);
    cudaGetSymbolAddress((void**)&p.paw, d_paw);
    cudaGetSymbolAddress((void**)&p.ebS, d_ebS);
    cudaGetSymbolAddress((void**)&p.alphaS, d_alphaS);
    cudaGetSymbolAddress((void**)&p.denA, d_denA);
    cudaGetSymbolAddress((void**)&p.denB, d_denB);
    cudaGetSymbolAddress((void**)&p.counts, d_counts);
    cudaGetSymbolAddress((void**)&p.cur, d_cur);
    cudaGetSymbolAddress((void**)&p.offs, d_offs);
    cudaGetSymbolAddress((void**)&p.csum, d_csum);
    cudaGetSymbolAddress((void**)&p.posA, d_posA);
    cudaGetSymbolAddress((void**)&p.posB, d_posB);
    cudaGetSymbolAddress((void**)&p.edge2, d_edge2);
}

static void run_layer(const Ptrs& p,
                      const float* A, int K, int ldw,
                      const float* Wi, const float* bi, const float* ai,
                      const float* Wo, const float* bo, const float* ao,
                      const float* g,
                      const int* rowp, const int* colp, const int* et,
                      float* outH)
{
    transpose_A<<<dim3((NN + 31) / 32, 4), dim3(32, 8)>>>(A, NN, K, p.At);
    prep_wt<<<dim3(128, 4), 128>>>(Wi, Wo, ldw, K, p.Wt);
    cudaMemsetAsync(p.psc, 0, NN * 8 * sizeof(float));
    dim3 gg((NN + 127) / 128, 4);
    gemm4<<<gg, 256>>>(p.At, NN, K, p.Wt, ai, ao,
                       p.uA, p.vA, p.uB, p.vB, p.psc);
    dim3 gr(RR, 2);
    relproj2<<<gr, 128>>>(g, Wi, bi, ai, Wo, bo, ao, ldw, 2 * K,
                          p.wA, p.wB, p.paw);
    cudaMemsetAsync(p.denA, 0, NN * 2 * sizeof(float));
    cudaMemsetAsync(p.denB, 0, NN * 2 * sizeof(float));
    pass_a2<<<(EE + 255) / 256, 256>>>(rowp, colp, et, p.posA, p.posB,
                                       p.psc, p.paw, p.ebS, p.denA, p.denB);
    alpha_k<<<(2 * EE + 255) / 256, 256>>>(p.edge2, p.ebS, p.denA, p.denB, p.alphaS);
    dim3 gb((NN + 7) / 8, 2);
    pass_b_csr<<<gb, 256>>>(p.edge2, p.alphaS, p.offs, p.counts,
                            p.uA, p.wA, p.accA, p.salA,
                            p.uB, p.wB, p.accB, p.salB);
    combine<<<NN, 128>>>(p.accA, p.salA, p.vA, p.accB, p.salB, p.vB, outH);
}
}  // namespace

extern "C" void kernel_launch(void* const* d_in, const int* in_sizes, int n_in,
                              void* d_out, int out_size)
{
    const float* x   = (const float*)d_in[0];
    const float* g   = (const float*)d_in[1];
    const int*   ei  = (const int*)d_in[2];
    const int*   et  = (const int*)d_in[3];
    const float* W1i = (const float*)d_in[4];
    const float* b1i = (const float*)d_in[5];
    const float* a1i = (const float*)d_in[6];
    const float* W1o = (const float*)d_in[7];
    const float* b1o = (const float*)d_in[8];
    const float* a1o = (const float*)d_in[9];
    const float* W2i = (const float*)d_in[10];
    const float* b2i = (const float*)d_in[11];
    const float* a2i = (const float*)d_in[12];
    const float* W2o = (const float*)d_in[13];
    const float* b2o = (const float*)d_in[14];
    const float* a2o = (const float*)d_in[15];
    const float* We  = (const float*)d_in[16];
    const float* be  = (const float*)d_in[17];
    const float* Wr  = (const float*)d_in[18];
    const float* br  = (const float*)d_in[19];
    float* out = (float*)d_out;

    const int* rowp = ei;
    const int* colp = ei + EE;

    Ptrs p;
    get_ptrs(p);

    // edge counting sort (once per call; shared by both layers & directions)
    const int M2 = 2 * NN;
    const int NB = (M2 + 511) / 512;
    cudaMemsetAsync(p.counts, 0, M2 * sizeof(int));
    cudaMemsetAsync(p.cur, 0, M2 * sizeof(int));
    hist_k<<<(EE + 255) / 256, 256>>>(rowp, colp, p.counts);
    scan1<<<NB, 512>>>(p.counts, p.offs, p.csum, M2);
    scan2<<<1, 256>>>(p.csum, NB);
    scan3<<<(M2 + 255) / 256, 256>>>(p.offs, p.csum, M2);
    scatter_k<<<(EE + 255) / 256, 256>>>(rowp, colp, et, p.offs, p.cur,
                                         p.edge2, p.posA, p.posB);

    norm_x<<<NN, 128>>>(x, p.xn);

    // layer 1: input xn [NN,100]
    run_layer(p, p.xn, XS, 2 * XS + GS,
              W1i, b1i, a1i, W1o, b1o, a1o, g, rowp, colp, et, p.h);

    // layer 2: input h [NN,128]
    run_layer(p, p.h, 128, 2 * 128 + GS,
              W2i, b2i, a2i, W2o, b2o, a2o, g, rowp, colp, et, p.h);

    // entity layer
    dim3 ge((NN + 63) / 64, 1);
    gemm_wt<<<ge, 256>>>(p.xn, XS, We, XS, XS, be, p.ent, 64, NN);

    final_k<<<NN, 128>>>(p.ent, p.h, out);
    relproj_out<<<RR, 128>>>(g, Wr, br, out + NN * 128);
}